// round 14
// baseline (speedup 1.0000x reference)
#include <cuda_runtime.h>
#include <cuda_fp16.h>
#include <cstdint>

#define Bc   2
#define Lc   2048
#define Dc   2048
#define Hc   16
#define KVHc 8
#define Dhc  128
#define QKVN 4096
#define D3c  6144
#define EPSc 1e-5f

// ---------------- scratch (device globals: allocation-guard safe) -------------
__device__ float  g_mod [Bc * D3c];
__device__ __half g_xmh [(size_t)Bc * Lc * Dc];
__device__ __half g_qkvh[(size_t)Bc * Lc * QKVN];  // 0..2047 Q | 2048..3071 K | 3072..4095 V
__device__ __half g_oh  [(size_t)Bc * Lc * Dc];
__device__ __half g_wTh [(size_t)QKVN * Dc];
__device__ __half g_woTh[(size_t)Dc * Dc];

// ================= helpers ====================================================
__device__ __forceinline__ uint32_t smem_u32(const void* p) {
    uint32_t a;
    asm("{ .reg .u64 t; cvta.to.shared.u64 t, %1; cvt.u32.u64 %0, t; }" : "=r"(a) : "l"(p));
    return a;
}
__device__ __forceinline__ void ldsm4(uint32_t* r, uint32_t a) {
    asm volatile("ldmatrix.sync.aligned.m8n8.x4.shared.b16 {%0,%1,%2,%3}, [%4];"
                 : "=r"(r[0]), "=r"(r[1]), "=r"(r[2]), "=r"(r[3]) : "r"(a));
}
__device__ __forceinline__ void ldsm4t(uint32_t* r, uint32_t a) {
    asm volatile("ldmatrix.sync.aligned.m8n8.x4.trans.shared.b16 {%0,%1,%2,%3}, [%4];"
                 : "=r"(r[0]), "=r"(r[1]), "=r"(r[2]), "=r"(r[3]) : "r"(a));
}
__device__ __forceinline__ void mma16(float* d, const uint32_t* a, uint32_t b0, uint32_t b1) {
    asm volatile("mma.sync.aligned.m16n8k16.row.col.f32.f16.f16.f32 "
                 "{%0,%1,%2,%3}, {%4,%5,%6,%7}, {%8,%9}, {%0,%1,%2,%3};"
                 : "+f"(d[0]), "+f"(d[1]), "+f"(d[2]), "+f"(d[3])
                 : "r"(a[0]), "r"(a[1]), "r"(a[2]), "r"(a[3]), "r"(b0), "r"(b1));
}
__device__ __forceinline__ void cpa16(uint32_t s, const void* g) {
    asm volatile("cp.async.cg.shared.global [%0], [%1], 16;" :: "r"(s), "l"(g));
}
__device__ __forceinline__ uint32_t pack2(float a, float b) {
    __half2 h = __floats2half2_rn(a, b);
    return *reinterpret_cast<uint32_t*>(&h);
}
#define CP_COMMIT() asm volatile("cp.async.commit_group;" ::: "memory")
#define CP_WAIT0()  asm volatile("cp.async.wait_group 0;" ::: "memory")
#define CP_WAIT1()  asm volatile("cp.async.wait_group 1;" ::: "memory")

// ================= kernel 1: mod = silu(temb) @ w_mod + b_mod =================
__global__ void k_mod(const float* __restrict__ temb, const float* __restrict__ w_mod,
                      const float* __restrict__ b_mod) {
    __shared__ float st[Dc];
    __shared__ float ps[4][64];
    int b = blockIdx.y;
    int tx = threadIdx.x & 63, ty = threadIdx.x >> 6;
    int j = blockIdx.x * 64 + tx;
    for (int i = threadIdx.x; i < Dc; i += 256) {
        float x = temb[b * Dc + i];
        st[i] = x / (1.f + __expf(-x));
    }
    __syncthreads();
    float acc = 0.f;
    int k0 = ty * 512;
#pragma unroll 4
    for (int i = 0; i < 512; i++)
        acc = fmaf(st[k0 + i], w_mod[(size_t)(k0 + i) * D3c + j], acc);
    ps[ty][tx] = acc;
    __syncthreads();
    if (ty == 0)
        g_mod[b * D3c + j] = ps[0][tx] + ps[1][tx] + ps[2][tx] + ps[3][tx] + b_mod[j];
}

// ====== kernel 2: xm = half(rmsnorm(x)*w_ln*(1+scale)+shift), float4 I/O ======
__global__ void k_rmsmod(const float* __restrict__ x, const float* __restrict__ w_ln) {
    int row = blockIdx.x;
    int b   = row >> 11;
    const float4* xr = (const float4*)(x + (size_t)row * Dc);
    int tid = threadIdx.x;

    float4 a0 = xr[tid], a1 = xr[tid + 256];
    float ss = a0.x*a0.x + a0.y*a0.y + a0.z*a0.z + a0.w*a0.w
             + a1.x*a1.x + a1.y*a1.y + a1.z*a1.z + a1.w*a1.w;
#pragma unroll
    for (int o = 16; o; o >>= 1) ss += __shfl_xor_sync(0xffffffffu, ss, o);
    __shared__ float red[8];
    __shared__ float sinv;
    if ((tid & 31) == 0) red[tid >> 5] = ss;
    __syncthreads();
    if (tid == 0) {
        float t = 0.f;
#pragma unroll
        for (int w = 0; w < 8; w++) t += red[w];
        sinv = rsqrtf(t * (1.f / Dc) + EPSc);
    }
    __syncthreads();
    float inv = sinv;
    const float4* shv = (const float4*)(g_mod + b * D3c);
    const float4* scv = shv + 512;
    const float4* wv  = (const float4*)w_ln;
    __half* xm = g_xmh + (size_t)row * Dc;
#pragma unroll
    for (int u = 0; u < 2; u++) {
        int i = tid + u * 256;
        float4 av = u ? a1 : a0;
        float4 w4 = wv[i], s4 = scv[i], h4 = shv[i];
        float o0 = fmaf(av.x * inv * w4.x, 1.f + s4.x, h4.x);
        float o1 = fmaf(av.y * inv * w4.y, 1.f + s4.y, h4.y);
        float o2 = fmaf(av.z * inv * w4.z, 1.f + s4.z, h4.z);
        float o3 = fmaf(av.w * inv * w4.w, 1.f + s4.w, h4.w);
        uint2 pk = make_uint2(pack2(o0, o1), pack2(o2, o3));
        *(uint2*)(xm + i * 4) = pk;
    }
}

// ====== batched transpose: all 4 weights in one launch ========================
__global__ void k_transpose4(const float* __restrict__ wq, const float* __restrict__ wk,
                             const float* __restrict__ wv, const float* __restrict__ wo) {
    __shared__ float t[32][33];
    const float* src; __half* dst; int N;
    switch (blockIdx.z) {
        case 0:  src = wq; dst = g_wTh;                         N = 2048; break;
        case 1:  src = wk; dst = g_wTh + (size_t)2048 * Dc;     N = 1024; break;
        case 2:  src = wv; dst = g_wTh + (size_t)3072 * Dc;     N = 1024; break;
        default: src = wo; dst = g_woTh;                        N = 2048; break;
    }
    int nb = blockIdx.x * 32;
    if (nb >= N) return;
    int kb = blockIdx.y * 32;
    int x = threadIdx.x, y = threadIdx.y;
#pragma unroll
    for (int i = 0; i < 32; i += 8)
        t[y + i][x] = src[(size_t)(kb + y + i) * N + nb + x];
    __syncthreads();
#pragma unroll
    for (int i = 0; i < 32; i += 8)
        dst[(size_t)(nb + y + i) * Dc + kb + x] = __float2half_rn(t[x][y + i]);
}

// ====== fp16 mma.sync GEMM (round-13, verified): BM=128 BN=128 BK=64 ==========
#define GSTAGE 36864
#define MMASMEM (GSTAGE * 3)         // 110592 bytes, 2 CTAs/SM

template<int EPI>
__global__ void __launch_bounds__(256, 2)
k_mma(const __half* __restrict__ Ag, const __half* __restrict__ Bg,
      void* __restrict__ Cv, int N, int K, const float* __restrict__ hid) {
    extern __shared__ __half sh[];
    uint32_t base = smem_u32(sh);
    int t = threadIdx.x, l = t & 31, wid = t >> 5;
    int wm = wid >> 2, wn = wid & 3;
    int m0 = blockIdx.y * 128, n0 = blockIdx.x * 128;

    auto loadT = [&](int kt, int buf) {
        uint32_t ab = base + buf * GSTAGE;
#pragma unroll
        for (int i = 0; i < 4; i++) {
            int p = t + (i << 8); int r = p >> 3, c = p & 7;
            cpa16(ab + (r * 72 + c * 8) * 2,
                  Ag + (size_t)(m0 + r) * K + kt * 64 + c * 8);
        }
#pragma unroll
        for (int i = 0; i < 4; i++) {
            int p = t + (i << 8); int r = p >> 3, c = p & 7;
            cpa16(ab + 18432 + (r * 72 + c * 8) * 2,
                  Bg + (size_t)(n0 + r) * K + kt * 64 + c * 8);
        }
    };

    float acc[4][4][4];
#pragma unroll
    for (int i = 0; i < 4; i++)
#pragma unroll
        for (int j = 0; j < 4; j++)
#pragma unroll
            for (int c = 0; c < 4; c++) acc[i][j][c] = 0.f;

    int nk = K >> 6;
    loadT(0, 0); CP_COMMIT();
    loadT(1, 1); CP_COMMIT();

    int cur = 0;
    for (int kt = 0; kt < nk; kt++) {
        if (kt + 1 < nk) CP_WAIT1(); else CP_WAIT0();
        __syncthreads();
        if (kt + 2 < nk) {
            int nb = cur + 2; if (nb >= 3) nb -= 3;
            loadT(kt + 2, nb);
            CP_COMMIT();
        }

        uint32_t Ab = base + cur * GSTAGE;
        uint32_t Bb = Ab + 18432;
#pragma unroll
        for (int kc2 = 0; kc2 < 2; kc2++) {
            uint32_t bb[4][4];
#pragma unroll
            for (int j = 0; j < 4; j++)
                ldsm4(bb[j], Bb + ((wn * 32 + j * 8 + (l & 7)) * 72
                                   + (kc2 * 4 + (l >> 3)) * 8) * 2);
#pragma unroll
            for (int kc = 0; kc < 2; kc++) {
                uint32_t aa[4][4];
#pragma unroll
                for (int i = 0; i < 4; i++)
                    ldsm4(aa[i], Ab + ((wm * 64 + i * 16 + ((l >> 3) & 1) * 8 + (l & 7)) * 72
                                       + (kc2 * 4 + 2 * kc + (l >> 4)) * 8) * 2);
#pragma unroll
                for (int i = 0; i < 4; i++)
#pragma unroll
                    for (int j = 0; j < 4; j++)
                        mma16(acc[i][j], aa[i], bb[j][2 * kc], bb[j][2 * kc + 1]);
            }
        }
        cur++; if (cur == 3) cur = 0;
    }

#pragma unroll
    for (int i = 0; i < 4; i++) {
        int gm = m0 + wm * 64 + i * 16 + (l >> 2);
#pragma unroll
        for (int j = 0; j < 4; j++) {
            int gn = n0 + wn * 32 + j * 8 + 2 * (l & 3);
            if (EPI == 0) {
                __half* C = (__half*)Cv;
                *(__half2*)(C + (size_t)gm * N + gn) =
                    __floats2half2_rn(acc[i][j][0], acc[i][j][1]);
                *(__half2*)(C + (size_t)(gm + 8) * N + gn) =
                    __floats2half2_rn(acc[i][j][2], acc[i][j][3]);
            } else {
                float* C = (float*)Cv;
                size_t o0 = (size_t)gm * N + gn;
                size_t o1 = (size_t)(gm + 8) * N + gn;
                int b0 = gm >> 11, b1 = (gm + 8) >> 11;
                float2 h0 = *(const float2*)(hid + o0);
                float2 h1 = *(const float2*)(hid + o1);
                float2 g0 = *(const float2*)(g_mod + b0 * D3c + 2 * Dc + gn);
                float2 g1 = *(const float2*)(g_mod + b1 * D3c + 2 * Dc + gn);
                *(float2*)(C + o0) = make_float2(fmaf(g0.x, acc[i][j][0], h0.x),
                                                 fmaf(g0.y, acc[i][j][1], h0.y));
                *(float2*)(C + o1) = make_float2(fmaf(g1.x, acc[i][j][2], h1.x),
                                                 fmaf(g1.y, acc[i][j][3], h1.y));
            }
        }
    }
}

// ====== per-head RMSNorm + mixed RoPE, vectorized (round-12, verified) ========
__global__ void __launch_bounds__(256)
k_qknorm_rope(const float* __restrict__ cos1d, const float* __restrict__ sin1d,
              const float* __restrict__ rope3d,
              const float* __restrict__ qn, const float* __restrict__ kn,
              const int* __restrict__ mp) {
    int warp = threadIdx.x >> 5, lane = threadIdx.x & 31;
    int v  = blockIdx.x * 8 + warp;
    int bl = v / 24, r = v % 24;
    int b = bl >> 11, l = bl & 2047;
    int d0 = lane * 4;

    __half* ptr; const float* w;
    if (r < Hc) { ptr = g_qkvh + (size_t)bl * QKVN + r * Dhc;               w = qn; }
    else        { ptr = g_qkvh + (size_t)bl * QKVN + 2048 + (r - Hc) * Dhc; w = kn; }

    __half2 h01 = *(const __half2*)(ptr + d0);
    __half2 h23 = *(const __half2*)(ptr + d0 + 2);
    float val[4] = { __half2float(h01.x), __half2float(h01.y),
                     __half2float(h23.x), __half2float(h23.y) };
    float ss = 0.f;
#pragma unroll
    for (int i = 0; i < 4; i++) ss = fmaf(val[i], val[i], ss);
#pragma unroll
    for (int o = 16; o; o >>= 1) ss += __shfl_xor_sync(0xffffffffu, ss, o);
    float inv = rsqrtf(ss * (1.f / Dhc) + EPSc);
    float4 wv4 = *(const float4*)(w + d0);
    val[0] *= inv * wv4.x; val[1] *= inv * wv4.y;
    val[2] *= inv * wv4.z; val[3] *= inv * wv4.w;

    bool is64 = (mp[1] == 0);
    bool in_full = false, in_img = false; int rel = 0;
#pragma unroll
    for (int m = 0; m < 2; m++) {
        int off, ln;
        if (is64) { off = mp[(b * 4 + m * 2) * 2]; ln = mp[(b * 4 + m * 2 + 1) * 2]; }
        else      { off = mp[b * 4 + m * 2];       ln = mp[b * 4 + m * 2 + 1]; }
        int seg_end = off + max(ln, 1);
        if (l >= off && l < seg_end) in_full = true;
        if (l >= off + 1 && l < off + ln) { in_img = true; rel += l - (off + 1); }
    }
    bool text = !in_full;
    bool img  = in_img && (rel < 1024);
    rel = min(max(rel, 0), 1023);

    float out[4];
    if (text) {
        float4 c4 = *(const float4*)(cos1d + l * Dhc + d0);
        float4 s4 = *(const float4*)(sin1d + l * Dhc + d0);
        float sgn = (d0 < 64) ? -1.f : 1.f;
        float cc[4] = {c4.x, c4.y, c4.z, c4.w};
        float s_[4] = {s4.x, s4.y, s4.z, s4.w};
#pragma unroll
        for (int i = 0; i < 4; i++) {
            float partner = __shfl_xor_sync(0xffffffffu, val[i], 16);
            out[i] = fmaf(val[i], cc[i], sgn * partner * s_[i]);
        }
    } else {
        const float4 R0 = *(const float4*)(rope3d + ((size_t)rel * 64 + 2 * lane) * 4);
        const float4 R1 = *(const float4*)(rope3d + ((size_t)rel * 64 + 2 * lane + 1) * 4);
        float o0 = fmaf(val[0], R0.x, val[1] * R0.z);
        float o1 = fmaf(val[0], R0.y, val[1] * R0.w);
        float o2 = fmaf(val[2], R1.x, val[3] * R1.z);
        float o3 = fmaf(val[2], R1.y, val[3] * R1.w);
        out[0] = img ? o0 : val[0]; out[1] = img ? o1 : val[1];
        out[2] = img ? o2 : val[2]; out[3] = img ? o3 : val[3];
    }
    *(__half2*)(ptr + d0)     = __floats2half2_rn(out[0], out[1]);
    *(__half2*)(ptr + d0 + 2) = __floats2half2_rn(out[2], out[3]);
}

// ====== flash attention, FA2-style; Q smem region reused by KV -> 3 CTAs/SM ===
// smem: stage s (s=0,1): K at s*34816 B, V at s*34816+17408 B. Q loads into
// stage 0 first, Qa fragments extracted, then KV(0) overwrites it.
#define FSMEM (34816 * 2)   // 69632 bytes -> 3 CTAs/SM

__global__ void __launch_bounds__(128, 3)
k_flash(__half* __restrict__ go) {
    extern __shared__ __half fh[];
    uint32_t base = smem_u32(fh);

    int t = threadIdx.x, l = t & 31, wid = t >> 5;
    int lo = l & 3, lr = l >> 2;
    int q0 = blockIdx.x << 6;
    int h  = blockIdx.y, b = blockIdx.z;
    int kh = h >> 1;
    const float SC = 0.08838834764831845f;

    const __half* qkv = g_qkvh;

    // --- Q into stage-0 front (64x136 halves), extract frags, then free it ---
#pragma unroll
    for (int i = 0; i < 8; i++) {
        int p = t + (i << 7); int r = p >> 4, c = p & 15;
        cpa16(base + (r * 136 + c * 8) * 2,
              qkv + (size_t)(b * Lc + q0 + r) * QKVN + h * Dhc + c * 8);
    }
    CP_COMMIT();
    CP_WAIT0();
    __syncthreads();

    uint32_t Qa[8][4];
#pragma unroll
    for (int kq = 0; kq < 8; kq++)
        ldsm4(Qa[kq], base + ((wid * 16 + ((l >> 3) & 1) * 8 + (l & 7)) * 136
                              + (kq * 2 + (l >> 4)) * 8) * 2);
    __syncthreads();   // all warps done reading Q; region may be overwritten

    auto loadKV = [&](int kt, int buf) {
        uint32_t sb = base + buf * 34816;   // bytes
#pragma unroll
        for (int i = 0; i < 8; i++) {
            int p = t + (i << 7); int r = p >> 4, c = p & 15;
            cpa16(sb + (r * 136 + c * 8) * 2,
                  qkv + (size_t)(b * Lc + kt * 64 + r) * QKVN + 2048 + kh * Dhc + c * 8);
        }
#pragma unroll
        for (int i = 0; i < 8; i++) {
            int p = t + (i << 7); int r = p >> 4, c = p & 15;
            cpa16(sb + 17408 + (r * 136 + c * 8) * 2,
                  qkv + (size_t)(b * Lc + kt * 64 + r) * QKVN + 3072 + kh * Dhc + c * 8);
        }
    };
    loadKV(0, 0); CP_COMMIT();
    loadKV(1, 1); CP_COMMIT();
    CP_WAIT1();
    __syncthreads();

    float accO[16][4];
    float m_run[2], l_run[2];
#pragma unroll
    for (int j = 0; j < 16; j++)
#pragma unroll
        for (int c = 0; c < 4; c++) accO[j][c] = 0.f;
    m_run[0] = m_run[1] = -1e30f;
    l_run[0] = l_run[1] = 0.f;

    for (int kt = 0; kt < 32; kt++) {
        int cur = kt & 1;
        uint32_t Kb = base + cur * 34816;
        uint32_t Vb = Kb + 17408;

        float accS[8][4];
#pragma unroll
        for (int j = 0; j < 8; j++)
#pragma unroll
            for (int c = 0; c < 4; c++) accS[j][c] = 0.f;
#pragma unroll
        for (int kc2 = 0; kc2 < 4; kc2++) {
            uint32_t bb[8][4];
#pragma unroll
            for (int nj = 0; nj < 8; nj++)
                ldsm4(bb[nj], Kb + ((nj * 8 + (l & 7)) * 136 + (kc2 * 4 + (l >> 3)) * 8) * 2);
#pragma unroll
            for (int kc = 0; kc < 2; kc++)
#pragma unroll
                for (int nj = 0; nj < 8; nj++)
                    mma16(accS[nj], Qa[kc2 * 2 + kc], bb[nj][2 * kc], bb[nj][2 * kc + 1]);
        }

        float pm[2], ps[2];
        pm[0] = pm[1] = -1e30f; ps[0] = ps[1] = 0.f;
#pragma unroll
        for (int nj = 0; nj < 8; nj++)
#pragma unroll
            for (int c = 0; c < 4; c++) {
                float v = accS[nj][c] * SC;
                accS[nj][c] = v;
                pm[c >> 1] = fmaxf(pm[c >> 1], v);
            }
#pragma unroll
        for (int r = 0; r < 2; r++) {
            pm[r] = fmaxf(pm[r], __shfl_xor_sync(0xffffffffu, pm[r], 1));
            pm[r] = fmaxf(pm[r], __shfl_xor_sync(0xffffffffu, pm[r], 2));
        }
#pragma unroll
        for (int nj = 0; nj < 8; nj++)
#pragma unroll
            for (int c = 0; c < 4; c++) {
                float p = __expf(accS[nj][c] - pm[c >> 1]);
                accS[nj][c] = p;
                ps[c >> 1] += p;
            }
#pragma unroll
        for (int r = 0; r < 2; r++) {
            ps[r] += __shfl_xor_sync(0xffffffffu, ps[r], 1);
            ps[r] += __shfl_xor_sync(0xffffffffu, ps[r], 2);
        }
        float cf[2], corr[2];
#pragma unroll
        for (int r = 0; r < 2; r++) {
            float mnew = fmaxf(m_run[r], pm[r]);
            corr[r] = __expf(m_run[r] - mnew);
            cf[r]   = __expf(pm[r] - mnew);
            l_run[r] = l_run[r] * corr[r] + ps[r] * cf[r];
            m_run[r] = mnew;
        }
#pragma unroll
        for (int nj = 0; nj < 16; nj++)
#pragma unroll
            for (int c = 0; c < 4; c++)
                accO[nj][c] *= corr[c >> 1];

        uint32_t Pa[4][4];
#pragma unroll
        for (int kc = 0; kc < 4; kc++) {
            Pa[kc][0] = pack2(accS[2*kc][0]   * cf[0], accS[2*kc][1]   * cf[0]);
            Pa[kc][1] = pack2(accS[2*kc][2]   * cf[1], accS[2*kc][3]   * cf[1]);
            Pa[kc][2] = pack2(accS[2*kc+1][0] * cf[0], accS[2*kc+1][1] * cf[0]);
            Pa[kc][3] = pack2(accS[2*kc+1][2] * cf[1], accS[2*kc+1][3] * cf[1]);
        }

#pragma unroll
        for (int kc2 = 0; kc2 < 2; kc2++)
#pragma unroll
            for (int nh = 0; nh < 2; nh++) {
                uint32_t bb[8][4];
#pragma unroll
                for (int nj = 0; nj < 8; nj++)
                    ldsm4t(bb[nj], Vb + ((kc2 * 32 + (l >> 3) * 8 + (l & 7)) * 136
                                         + (nh * 8 + nj) * 8) * 2);
#pragma unroll
                for (int kc = 0; kc < 2; kc++)
#pragma unroll
                    for (int nj = 0; nj < 8; nj++)
                        mma16(accO[nh * 8 + nj], Pa[kc2 * 2 + kc],
                              bb[nj][2 * kc], bb[nj][2 * kc + 1]);
            }

        if (kt < 31) {
            CP_WAIT0();
            __syncthreads();
            if (kt < 30) { loadKV(kt + 2, cur); CP_COMMIT(); }
        }
    }

    float inv0 = 1.f / l_run[0], inv1 = 1.f / l_run[1];
    int row0 = q0 + wid * 16 + lr;
#pragma unroll
    for (int nj = 0; nj < 16; nj++) {
        int col = h * Dhc + nj * 8 + 2 * lo;
        *(__half2*)(go + (size_t)(b * Lc + row0) * Dc + col) =
            __floats2half2_rn(accO[nj][0] * inv0, accO[nj][1] * inv0);
        *(__half2*)(go + (size_t)(b * Lc + row0 + 8) * Dc + col) =
            __floats2half2_rn(accO[nj][2] * inv1, accO[nj][3] * inv1);
    }
}

// ================================ host ========================================
extern "C" void kernel_launch(void* const* d_in, const int* in_sizes, int n_in,
                              void* d_out, int out_size) {
    const float* hidden = (const float*)d_in[0];
    const float* temb   = (const float*)d_in[1];
    const float* w_ln   = (const float*)d_in[2];
    const float* w_mod  = (const float*)d_in[3];
    const float* b_mod  = (const float*)d_in[4];
    const float* wq     = (const float*)d_in[5];
    const float* wk     = (const float*)d_in[6];
    const float* wv     = (const float*)d_in[7];
    const float* wo     = (const float*)d_in[8];
    const float* qn     = (const float*)d_in[9];
    const float* kn     = (const float*)d_in[10];
    const float* cos1   = (const float*)d_in[11];
    const float* sin1   = (const float*)d_in[12];
    const float* rope3  = (const float*)d_in[13];
    const int*   mpos   = (const int*)d_in[14];
    float* out = (float*)d_out;

    void *pxm, *pqkv, *po, *pwT, *pwoT;
    cudaGetSymbolAddress(&pxm,  g_xmh);
    cudaGetSymbolAddress(&pqkv, g_qkvh);
    cudaGetSymbolAddress(&po,   g_oh);
    cudaGetSymbolAddress(&pwT,  g_wTh);
    cudaGetSymbolAddress(&pwoT, g_woTh);

    cudaFuncSetAttribute(k_mma<0>, cudaFuncAttributeMaxDynamicSharedMemorySize, MMASMEM);
    cudaFuncSetAttribute(k_mma<1>, cudaFuncAttributeMaxDynamicSharedMemorySize, MMASMEM);
    cudaFuncSetAttribute(k_flash, cudaFuncAttributeMaxDynamicSharedMemorySize, FSMEM);

    k_mod<<<dim3(D3c / 64, Bc), 256>>>(temb, w_mod, b_mod);
    k_rmsmod<<<Bc * Lc, 256>>>(hidden, w_ln);

    k_transpose4<<<dim3(64, 64, 4), dim3(32, 8)>>>(wq, wk, wv, wo);

    // fused QKV GEMM: [4096 x 4096] = xm @ [wq|wk|wv]^T  (half out)
    k_mma<0><<<dim3(QKVN / 128, (Bc * Lc) / 128), 256, MMASMEM>>>(
        (const __half*)pxm, (const __half*)pwT, pqkv, QKVN, Dc, nullptr);

    k_qknorm_rope<<<(Bc * Lc * (Hc + KVHc)) / 8, 256>>>(cos1, sin1, rope3, qn, kn, mpos);

    k_flash<<<dim3(Lc / 64, Hc, Bc), 128, FSMEM>>>((__half*)po);

    // output projection + residual/gate epilogue (float out)
    k_mma<1><<<dim3(Dc / 128, (Bc * Lc) / 128), 256, MMASMEM>>>(
        (const __half*)po, (const __half*)pwoT, out, Dc, Dc, hidden);
}

// round 15
// speedup vs baseline: 1.0253x; 1.0253x over previous
#include <cuda_runtime.h>
#include <cuda_fp16.h>
#include <cstdint>

#define Bc   2
#define Lc   2048
#define Dc   2048
#define Hc   16
#define KVHc 8
#define Dhc  128
#define QKVN 4096
#define D3c  6144
#define EPSc 1e-5f

// ---------------- scratch (device globals: allocation-guard safe) -------------
__device__ float  g_mod [Bc * D3c];
__device__ __half g_xmh [(size_t)Bc * Lc * Dc];
__device__ __half g_qkvh[(size_t)Bc * Lc * QKVN];  // 0..2047 Q | 2048..3071 K | 3072..4095 V
__device__ __half g_oh  [(size_t)Bc * Lc * Dc];
__device__ __half g_wTh [(size_t)QKVN * Dc];
__device__ __half g_woTh[(size_t)Dc * Dc];

// ================= helpers ====================================================
__device__ __forceinline__ uint32_t smem_u32(const void* p) {
    uint32_t a;
    asm("{ .reg .u64 t; cvta.to.shared.u64 t, %1; cvt.u32.u64 %0, t; }" : "=r"(a) : "l"(p));
    return a;
}
__device__ __forceinline__ void ldsm4(uint32_t* r, uint32_t a) {
    asm volatile("ldmatrix.sync.aligned.m8n8.x4.shared.b16 {%0,%1,%2,%3}, [%4];"
                 : "=r"(r[0]), "=r"(r[1]), "=r"(r[2]), "=r"(r[3]) : "r"(a));
}
__device__ __forceinline__ void ldsm4t(uint32_t* r, uint32_t a) {
    asm volatile("ldmatrix.sync.aligned.m8n8.x4.trans.shared.b16 {%0,%1,%2,%3}, [%4];"
                 : "=r"(r[0]), "=r"(r[1]), "=r"(r[2]), "=r"(r[3]) : "r"(a));
}
__device__ __forceinline__ void mma16(float* d, const uint32_t* a, uint32_t b0, uint32_t b1) {
    asm volatile("mma.sync.aligned.m16n8k16.row.col.f32.f16.f16.f32 "
                 "{%0,%1,%2,%3}, {%4,%5,%6,%7}, {%8,%9}, {%0,%1,%2,%3};"
                 : "+f"(d[0]), "+f"(d[1]), "+f"(d[2]), "+f"(d[3])
                 : "r"(a[0]), "r"(a[1]), "r"(a[2]), "r"(a[3]), "r"(b0), "r"(b1));
}
__device__ __forceinline__ void cpa16(uint32_t s, const void* g) {
    asm volatile("cp.async.cg.shared.global [%0], [%1], 16;" :: "r"(s), "l"(g));
}
__device__ __forceinline__ uint32_t pack2(float a, float b) {
    __half2 h = __floats2half2_rn(a, b);
    return *reinterpret_cast<uint32_t*>(&h);
}
#define CP_COMMIT() asm volatile("cp.async.commit_group;" ::: "memory")
#define CP_WAIT0()  asm volatile("cp.async.wait_group 0;" ::: "memory")
#define CP_WAIT1()  asm volatile("cp.async.wait_group 1;" ::: "memory")

// ================= kernel 1: mod = silu(temb) @ w_mod + b_mod =================
__global__ void k_mod(const float* __restrict__ temb, const float* __restrict__ w_mod,
                      const float* __restrict__ b_mod) {
    __shared__ float st[Dc];
    __shared__ float ps[4][64];
    int b = blockIdx.y;
    int tx = threadIdx.x & 63, ty = threadIdx.x >> 6;
    int j = blockIdx.x * 64 + tx;
    for (int i = threadIdx.x; i < Dc; i += 256) {
        float x = temb[b * Dc + i];
        st[i] = x / (1.f + __expf(-x));
    }
    __syncthreads();
    float acc = 0.f;
    int k0 = ty * 512;
#pragma unroll 4
    for (int i = 0; i < 512; i++)
        acc = fmaf(st[k0 + i], w_mod[(size_t)(k0 + i) * D3c + j], acc);
    ps[ty][tx] = acc;
    __syncthreads();
    if (ty == 0)
        g_mod[b * D3c + j] = ps[0][tx] + ps[1][tx] + ps[2][tx] + ps[3][tx] + b_mod[j];
}

// ====== kernel 2: xm = half(rmsnorm(x)*w_ln*(1+scale)+shift), float4 I/O ======
__global__ void k_rmsmod(const float* __restrict__ x, const float* __restrict__ w_ln) {
    int row = blockIdx.x;
    int b   = row >> 11;
    const float4* xr = (const float4*)(x + (size_t)row * Dc);
    int tid = threadIdx.x;

    float4 a0 = xr[tid], a1 = xr[tid + 256];
    float ss = a0.x*a0.x + a0.y*a0.y + a0.z*a0.z + a0.w*a0.w
             + a1.x*a1.x + a1.y*a1.y + a1.z*a1.z + a1.w*a1.w;
#pragma unroll
    for (int o = 16; o; o >>= 1) ss += __shfl_xor_sync(0xffffffffu, ss, o);
    __shared__ float red[8];
    __shared__ float sinv;
    if ((tid & 31) == 0) red[tid >> 5] = ss;
    __syncthreads();
    if (tid == 0) {
        float t = 0.f;
#pragma unroll
        for (int w = 0; w < 8; w++) t += red[w];
        sinv = rsqrtf(t * (1.f / Dc) + EPSc);
    }
    __syncthreads();
    float inv = sinv;
    const float4* shv = (const float4*)(g_mod + b * D3c);
    const float4* scv = shv + 512;
    const float4* wv  = (const float4*)w_ln;
    __half* xm = g_xmh + (size_t)row * Dc;
#pragma unroll
    for (int u = 0; u < 2; u++) {
        int i = tid + u * 256;
        float4 av = u ? a1 : a0;
        float4 w4 = wv[i], s4 = scv[i], h4 = shv[i];
        float o0 = fmaf(av.x * inv * w4.x, 1.f + s4.x, h4.x);
        float o1 = fmaf(av.y * inv * w4.y, 1.f + s4.y, h4.y);
        float o2 = fmaf(av.z * inv * w4.z, 1.f + s4.z, h4.z);
        float o3 = fmaf(av.w * inv * w4.w, 1.f + s4.w, h4.w);
        uint2 pk = make_uint2(pack2(o0, o1), pack2(o2, o3));
        *(uint2*)(xm + i * 4) = pk;
    }
}

// ====== batched transpose: all 4 weights in one launch ========================
__global__ void k_transpose4(const float* __restrict__ wq, const float* __restrict__ wk,
                             const float* __restrict__ wv, const float* __restrict__ wo) {
    __shared__ float t[32][33];
    const float* src; __half* dst; int N;
    switch (blockIdx.z) {
        case 0:  src = wq; dst = g_wTh;                         N = 2048; break;
        case 1:  src = wk; dst = g_wTh + (size_t)2048 * Dc;     N = 1024; break;
        case 2:  src = wv; dst = g_wTh + (size_t)3072 * Dc;     N = 1024; break;
        default: src = wo; dst = g_woTh;                        N = 2048; break;
    }
    int nb = blockIdx.x * 32;
    if (nb >= N) return;
    int kb = blockIdx.y * 32;
    int x = threadIdx.x, y = threadIdx.y;
#pragma unroll
    for (int i = 0; i < 32; i += 8)
        t[y + i][x] = src[(size_t)(kb + y + i) * N + nb + x];
    __syncthreads();
#pragma unroll
    for (int i = 0; i < 32; i += 8)
        dst[(size_t)(nb + y + i) * Dc + kb + x] = __float2half_rn(t[x][y + i]);
}

// ====== fp16 mma.sync GEMM (round-13, verified): BM=128 BN=128 BK=64 ==========
#define GSTAGE 36864
#define MMASMEM (GSTAGE * 3)         // 110592 bytes, 2 CTAs/SM

template<int EPI>
__global__ void __launch_bounds__(256, 2)
k_mma(const __half* __restrict__ Ag, const __half* __restrict__ Bg,
      void* __restrict__ Cv, int N, int K, const float* __restrict__ hid) {
    extern __shared__ __half sh[];
    uint32_t base = smem_u32(sh);
    int t = threadIdx.x, l = t & 31, wid = t >> 5;
    int wm = wid >> 2, wn = wid & 3;
    int m0 = blockIdx.y * 128, n0 = blockIdx.x * 128;

    auto loadT = [&](int kt, int buf) {
        uint32_t ab = base + buf * GSTAGE;
#pragma unroll
        for (int i = 0; i < 4; i++) {
            int p = t + (i << 8); int r = p >> 3, c = p & 7;
            cpa16(ab + (r * 72 + c * 8) * 2,
                  Ag + (size_t)(m0 + r) * K + kt * 64 + c * 8);
        }
#pragma unroll
        for (int i = 0; i < 4; i++) {
            int p = t + (i << 8); int r = p >> 3, c = p & 7;
            cpa16(ab + 18432 + (r * 72 + c * 8) * 2,
                  Bg + (size_t)(n0 + r) * K + kt * 64 + c * 8);
        }
    };

    float acc[4][4][4];
#pragma unroll
    for (int i = 0; i < 4; i++)
#pragma unroll
        for (int j = 0; j < 4; j++)
#pragma unroll
            for (int c = 0; c < 4; c++) acc[i][j][c] = 0.f;

    int nk = K >> 6;
    loadT(0, 0); CP_COMMIT();
    loadT(1, 1); CP_COMMIT();

    int cur = 0;
    for (int kt = 0; kt < nk; kt++) {
        if (kt + 1 < nk) CP_WAIT1(); else CP_WAIT0();
        __syncthreads();
        if (kt + 2 < nk) {
            int nb = cur + 2; if (nb >= 3) nb -= 3;
            loadT(kt + 2, nb);
            CP_COMMIT();
        }

        uint32_t Ab = base + cur * GSTAGE;
        uint32_t Bb = Ab + 18432;
#pragma unroll
        for (int kc2 = 0; kc2 < 2; kc2++) {
            uint32_t bb[4][4];
#pragma unroll
            for (int j = 0; j < 4; j++)
                ldsm4(bb[j], Bb + ((wn * 32 + j * 8 + (l & 7)) * 72
                                   + (kc2 * 4 + (l >> 3)) * 8) * 2);
#pragma unroll
            for (int kc = 0; kc < 2; kc++) {
                uint32_t aa[4][4];
#pragma unroll
                for (int i = 0; i < 4; i++)
                    ldsm4(aa[i], Ab + ((wm * 64 + i * 16 + ((l >> 3) & 1) * 8 + (l & 7)) * 72
                                       + (kc2 * 4 + 2 * kc + (l >> 4)) * 8) * 2);
#pragma unroll
                for (int i = 0; i < 4; i++)
#pragma unroll
                    for (int j = 0; j < 4; j++)
                        mma16(acc[i][j], aa[i], bb[j][2 * kc], bb[j][2 * kc + 1]);
            }
        }
        cur++; if (cur == 3) cur = 0;
    }

#pragma unroll
    for (int i = 0; i < 4; i++) {
        int gm = m0 + wm * 64 + i * 16 + (l >> 2);
#pragma unroll
        for (int j = 0; j < 4; j++) {
            int gn = n0 + wn * 32 + j * 8 + 2 * (l & 3);
            if (EPI == 0) {
                __half* C = (__half*)Cv;
                *(__half2*)(C + (size_t)gm * N + gn) =
                    __floats2half2_rn(acc[i][j][0], acc[i][j][1]);
                *(__half2*)(C + (size_t)(gm + 8) * N + gn) =
                    __floats2half2_rn(acc[i][j][2], acc[i][j][3]);
            } else {
                float* C = (float*)Cv;
                size_t o0 = (size_t)gm * N + gn;
                size_t o1 = (size_t)(gm + 8) * N + gn;
                int b0 = gm >> 11, b1 = (gm + 8) >> 11;
                float2 h0 = *(const float2*)(hid + o0);
                float2 h1 = *(const float2*)(hid + o1);
                float2 g0 = *(const float2*)(g_mod + b0 * D3c + 2 * Dc + gn);
                float2 g1 = *(const float2*)(g_mod + b1 * D3c + 2 * Dc + gn);
                *(float2*)(C + o0) = make_float2(fmaf(g0.x, acc[i][j][0], h0.x),
                                                 fmaf(g0.y, acc[i][j][1], h0.y));
                *(float2*)(C + o1) = make_float2(fmaf(g1.x, acc[i][j][2], h1.x),
                                                 fmaf(g1.y, acc[i][j][3], h1.y));
            }
        }
    }
}

// ====== per-head RMSNorm + mixed RoPE, vectorized (round-12, verified) ========
__global__ void __launch_bounds__(256)
k_qknorm_rope(const float* __restrict__ cos1d, const float* __restrict__ sin1d,
              const float* __restrict__ rope3d,
              const float* __restrict__ qn, const float* __restrict__ kn,
              const int* __restrict__ mp) {
    int warp = threadIdx.x >> 5, lane = threadIdx.x & 31;
    int v  = blockIdx.x * 8 + warp;
    int bl = v / 24, r = v % 24;
    int b = bl >> 11, l = bl & 2047;
    int d0 = lane * 4;

    __half* ptr; const float* w;
    if (r < Hc) { ptr = g_qkvh + (size_t)bl * QKVN + r * Dhc;               w = qn; }
    else        { ptr = g_qkvh + (size_t)bl * QKVN + 2048 + (r - Hc) * Dhc; w = kn; }

    __half2 h01 = *(const __half2*)(ptr + d0);
    __half2 h23 = *(const __half2*)(ptr + d0 + 2);
    float val[4] = { __half2float(h01.x), __half2float(h01.y),
                     __half2float(h23.x), __half2float(h23.y) };
    float ss = 0.f;
#pragma unroll
    for (int i = 0; i < 4; i++) ss = fmaf(val[i], val[i], ss);
#pragma unroll
    for (int o = 16; o; o >>= 1) ss += __shfl_xor_sync(0xffffffffu, ss, o);
    float inv = rsqrtf(ss * (1.f / Dhc) + EPSc);
    float4 wv4 = *(const float4*)(w + d0);
    val[0] *= inv * wv4.x; val[1] *= inv * wv4.y;
    val[2] *= inv * wv4.z; val[3] *= inv * wv4.w;

    bool is64 = (mp[1] == 0);
    bool in_full = false, in_img = false; int rel = 0;
#pragma unroll
    for (int m = 0; m < 2; m++) {
        int off, ln;
        if (is64) { off = mp[(b * 4 + m * 2) * 2]; ln = mp[(b * 4 + m * 2 + 1) * 2]; }
        else      { off = mp[b * 4 + m * 2];       ln = mp[b * 4 + m * 2 + 1]; }
        int seg_end = off + max(ln, 1);
        if (l >= off && l < seg_end) in_full = true;
        if (l >= off + 1 && l < off + ln) { in_img = true; rel += l - (off + 1); }
    }
    bool text = !in_full;
    bool img  = in_img && (rel < 1024);
    rel = min(max(rel, 0), 1023);

    float out[4];
    if (text) {
        float4 c4 = *(const float4*)(cos1d + l * Dhc + d0);
        float4 s4 = *(const float4*)(sin1d + l * Dhc + d0);
        float sgn = (d0 < 64) ? -1.f : 1.f;
        float cc[4] = {c4.x, c4.y, c4.z, c4.w};
        float s_[4] = {s4.x, s4.y, s4.z, s4.w};
#pragma unroll
        for (int i = 0; i < 4; i++) {
            float partner = __shfl_xor_sync(0xffffffffu, val[i], 16);
            out[i] = fmaf(val[i], cc[i], sgn * partner * s_[i]);
        }
    } else {
        const float4 R0 = *(const float4*)(rope3d + ((size_t)rel * 64 + 2 * lane) * 4);
        const float4 R1 = *(const float4*)(rope3d + ((size_t)rel * 64 + 2 * lane + 1) * 4);
        float o0 = fmaf(val[0], R0.x, val[1] * R0.z);
        float o1 = fmaf(val[0], R0.y, val[1] * R0.w);
        float o2 = fmaf(val[2], R1.x, val[3] * R1.z);
        float o3 = fmaf(val[2], R1.y, val[3] * R1.w);
        out[0] = img ? o0 : val[0]; out[1] = img ? o1 : val[1];
        out[2] = img ? o2 : val[2]; out[3] = img ? o3 : val[3];
    }
    *(__half2*)(ptr + d0)     = __floats2half2_rn(out[0], out[1]);
    *(__half2*)(ptr + d0 + 2) = __floats2half2_rn(out[2], out[3]);
}

// ====== flash attention, FA2-style (round-13 exact, verified) =================
// CTA: 64 q-rows x 1 head, 4 warps. P register-resident. Q frags preloaded.
// ONE __syncthreads per kv-iter. 87 KB smem -> 2 CTAs/SM, no reg cap.
#define FSMEM (43520 * 2)   // 87040 bytes

__global__ void __launch_bounds__(128)
k_flash(__half* __restrict__ go) {
    extern __shared__ __half fh[];
    uint32_t base = smem_u32(fh);

    int t = threadIdx.x, l = t & 31, wid = t >> 5;
    int lo = l & 3, lr = l >> 2;
    int q0 = blockIdx.x << 6;
    int h  = blockIdx.y, b = blockIdx.z;
    int kh = h >> 1;
    const float SC = 0.08838834764831845f;

    const __half* qkv = g_qkvh;

#pragma unroll
    for (int i = 0; i < 8; i++) {
        int p = t + (i << 7); int r = p >> 4, c = p & 15;
        cpa16(base + (r * 136 + c * 8) * 2,
              qkv + (size_t)(b * Lc + q0 + r) * QKVN + h * Dhc + c * 8);
    }
    auto loadKV = [&](int kt, int buf) {
        uint32_t sb = base + (8704 + buf * 17408) * 2;
#pragma unroll
        for (int i = 0; i < 8; i++) {
            int p = t + (i << 7); int r = p >> 4, c = p & 15;
            cpa16(sb + (r * 136 + c * 8) * 2,
                  qkv + (size_t)(b * Lc + kt * 64 + r) * QKVN + 2048 + kh * Dhc + c * 8);
        }
#pragma unroll
        for (int i = 0; i < 8; i++) {
            int p = t + (i << 7); int r = p >> 4, c = p & 15;
            cpa16(sb + (8704 + r * 136 + c * 8) * 2,
                  qkv + (size_t)(b * Lc + kt * 64 + r) * QKVN + 3072 + kh * Dhc + c * 8);
        }
    };
    loadKV(0, 0); CP_COMMIT();
    loadKV(1, 1); CP_COMMIT();
    CP_WAIT1();
    __syncthreads();

    uint32_t Qa[8][4];
#pragma unroll
    for (int kq = 0; kq < 8; kq++)
        ldsm4(Qa[kq], base + ((wid * 16 + ((l >> 3) & 1) * 8 + (l & 7)) * 136
                              + (kq * 2 + (l >> 4)) * 8) * 2);

    float accO[16][4];
    float m_run[2], l_run[2];
#pragma unroll
    for (int j = 0; j < 16; j++)
#pragma unroll
        for (int c = 0; c < 4; c++) accO[j][c] = 0.f;
    m_run[0] = m_run[1] = -1e30f;
    l_run[0] = l_run[1] = 0.f;

    for (int kt = 0; kt < 32; kt++) {
        int cur = kt & 1;
        uint32_t Kb = base + (8704 + cur * 17408) * 2;
        uint32_t Vb = Kb + 8704 * 2;

        float accS[8][4];
#pragma unroll
        for (int j = 0; j < 8; j++)
#pragma unroll
            for (int c = 0; c < 4; c++) accS[j][c] = 0.f;
#pragma unroll
        for (int kc2 = 0; kc2 < 4; kc2++) {
            uint32_t bb[8][4];
#pragma unroll
            for (int nj = 0; nj < 8; nj++)
                ldsm4(bb[nj], Kb + ((nj * 8 + (l & 7)) * 136 + (kc2 * 4 + (l >> 3)) * 8) * 2);
#pragma unroll
            for (int kc = 0; kc < 2; kc++)
#pragma unroll
                for (int nj = 0; nj < 8; nj++)
                    mma16(accS[nj], Qa[kc2 * 2 + kc], bb[nj][2 * kc], bb[nj][2 * kc + 1]);
        }

        float pm[2], ps[2];
        pm[0] = pm[1] = -1e30f; ps[0] = ps[1] = 0.f;
#pragma unroll
        for (int nj = 0; nj < 8; nj++)
#pragma unroll
            for (int c = 0; c < 4; c++) {
                float v = accS[nj][c] * SC;
                accS[nj][c] = v;
                pm[c >> 1] = fmaxf(pm[c >> 1], v);
            }
#pragma unroll
        for (int r = 0; r < 2; r++) {
            pm[r] = fmaxf(pm[r], __shfl_xor_sync(0xffffffffu, pm[r], 1));
            pm[r] = fmaxf(pm[r], __shfl_xor_sync(0xffffffffu, pm[r], 2));
        }
#pragma unroll
        for (int nj = 0; nj < 8; nj++)
#pragma unroll
            for (int c = 0; c < 4; c++) {
                float p = __expf(accS[nj][c] - pm[c >> 1]);
                accS[nj][c] = p;
                ps[c >> 1] += p;
            }
#pragma unroll
        for (int r = 0; r < 2; r++) {
            ps[r] += __shfl_xor_sync(0xffffffffu, ps[r], 1);
            ps[r] += __shfl_xor_sync(0xffffffffu, ps[r], 2);
        }
        float cf[2], corr[2];
#pragma unroll
        for (int r = 0; r < 2; r++) {
            float mnew = fmaxf(m_run[r], pm[r]);
            corr[r] = __expf(m_run[r] - mnew);
            cf[r]   = __expf(pm[r] - mnew);
            l_run[r] = l_run[r] * corr[r] + ps[r] * cf[r];
            m_run[r] = mnew;
        }
#pragma unroll
        for (int nj = 0; nj < 16; nj++)
#pragma unroll
            for (int c = 0; c < 4; c++)
                accO[nj][c] *= corr[c >> 1];

        uint32_t Pa[4][4];
#pragma unroll
        for (int kc = 0; kc < 4; kc++) {
            Pa[kc][0] = pack2(accS[2*kc][0]   * cf[0], accS[2*kc][1]   * cf[0]);
            Pa[kc][1] = pack2(accS[2*kc][2]   * cf[1], accS[2*kc][3]   * cf[1]);
            Pa[kc][2] = pack2(accS[2*kc+1][0] * cf[0], accS[2*kc+1][1] * cf[0]);
            Pa[kc][3] = pack2(accS[2*kc+1][2] * cf[1], accS[2*kc+1][3] * cf[1]);
        }

#pragma unroll
        for (int kc2 = 0; kc2 < 2; kc2++)
#pragma unroll
            for (int nh = 0; nh < 2; nh++) {
                uint32_t bb[8][4];
#pragma unroll
                for (int nj = 0; nj < 8; nj++)
                    ldsm4t(bb[nj], Vb + ((kc2 * 32 + (l >> 3) * 8 + (l & 7)) * 136
                                         + (nh * 8 + nj) * 8) * 2);
#pragma unroll
                for (int kc = 0; kc < 2; kc++)
#pragma unroll
                    for (int nj = 0; nj < 8; nj++)
                        mma16(accO[nh * 8 + nj], Pa[kc2 * 2 + kc],
                              bb[nj][2 * kc], bb[nj][2 * kc + 1]);
            }

        if (kt < 31) {
            CP_WAIT0();
            __syncthreads();
            if (kt < 30) { loadKV(kt + 2, cur); CP_COMMIT(); }
        }
    }

    float inv0 = 1.f / l_run[0], inv1 = 1.f / l_run[1];
    int row0 = q0 + wid * 16 + lr;
#pragma unroll
    for (int nj = 0; nj < 16; nj++) {
        int col = h * Dhc + nj * 8 + 2 * lo;
        *(__half2*)(go + (size_t)(b * Lc + row0) * Dc + col) =
            __floats2half2_rn(accO[nj][0] * inv0, accO[nj][1] * inv0);
        *(__half2*)(go + (size_t)(b * Lc + row0 + 8) * Dc + col) =
            __floats2half2_rn(accO[nj][2] * inv1, accO[nj][3] * inv1);
    }
}

// ================================ host ========================================
extern "C" void kernel_launch(void* const* d_in, const int* in_sizes, int n_in,
                              void* d_out, int out_size) {
    const float* hidden = (const float*)d_in[0];
    const float* temb   = (const float*)d_in[1];
    const float* w_ln   = (const float*)d_in[2];
    const float* w_mod  = (const float*)d_in[3];
    const float* b_mod  = (const float*)d_in[4];
    const float* wq     = (const float*)d_in[5];
    const float* wk     = (const float*)d_in[6];
    const float* wv     = (const float*)d_in[7];
    const float* wo     = (const float*)d_in[8];
    const float* qn     = (const float*)d_in[9];
    const float* kn     = (const float*)d_in[10];
    const float* cos1   = (const float*)d_in[11];
    const float* sin1   = (const float*)d_in[12];
    const float* rope3  = (const float*)d_in[13];
    const int*   mpos   = (const int*)d_in[14];
    float* out = (float*)d_out;

    void *pxm, *pqkv, *po, *pwT, *pwoT;
    cudaGetSymbolAddress(&pxm,  g_xmh);
    cudaGetSymbolAddress(&pqkv, g_qkvh);
    cudaGetSymbolAddress(&po,   g_oh);
    cudaGetSymbolAddress(&pwT,  g_wTh);
    cudaGetSymbolAddress(&pwoT, g_woTh);

    cudaFuncSetAttribute(k_mma<0>, cudaFuncAttributeMaxDynamicSharedMemorySize, MMASMEM);
    cudaFuncSetAttribute(k_mma<1>, cudaFuncAttributeMaxDynamicSharedMemorySize, MMASMEM);
    cudaFuncSetAttribute(k_flash, cudaFuncAttributeMaxDynamicSharedMemorySize, FSMEM);

    k_mod<<<dim3(D3c / 64, Bc), 256>>>(temb, w_mod, b_mod);
    k_rmsmod<<<Bc * Lc, 256>>>(hidden, w_ln);

    k_transpose4<<<dim3(64, 64, 4), dim3(32, 8)>>>(wq, wk, wv, wo);

    // fused QKV GEMM: [4096 x 4096] = xm @ [wq|wk|wv]^T  (half out)
    k_mma<0><<<dim3(QKVN / 128, (Bc * Lc) / 128), 256, MMASMEM>>>(
        (const __half*)pxm, (const __half*)pwT, pqkv, QKVN, Dc, nullptr);

    k_qknorm_rope<<<(Bc * Lc * (Hc + KVHc)) / 8, 256>>>(cos1, sin1, rope3, qn, kn, mpos);

    k_flash<<<dim3(Lc / 64, Hc, Bc), 128, FSMEM>>>((__half*)po);

    // output projection + residual/gate epilogue (float out)
    k_mma<1><<<dim3(Dc / 128, (Bc * Lc) / 128), 256, MMASMEM>>>(
        (const __half*)po, (const __half*)pwoT, out, Dc, Dc, hidden);
}

// round 16
// speedup vs baseline: 1.0269x; 1.0015x over previous
#include <cuda_runtime.h>
#include <cuda_fp16.h>
#include <cstdint>

#define Bc   2
#define Lc   2048
#define Dc   2048
#define Hc   16
#define KVHc 8
#define Dhc  128
#define QKVN 4096
#define D3c  6144
#define EPSc 1e-5f

// ---------------- scratch (device globals: allocation-guard safe) -------------
__device__ float  g_mod [Bc * D3c];
__device__ __half g_xmh [(size_t)Bc * Lc * Dc];
__device__ __half g_qkvh[(size_t)Bc * Lc * QKVN];  // 0..2047 Q | 2048..3071 K | 3072..4095 V
__device__ __half g_oh  [(size_t)Bc * Lc * Dc];
__device__ __half g_wTh [(size_t)QKVN * Dc];
__device__ __half g_woTh[(size_t)Dc * Dc];

// ================= helpers ====================================================
__device__ __forceinline__ uint32_t smem_u32(const void* p) {
    uint32_t a;
    asm("{ .reg .u64 t; cvta.to.shared.u64 t, %1; cvt.u32.u64 %0, t; }" : "=r"(a) : "l"(p));
    return a;
}
__device__ __forceinline__ void ldsm4(uint32_t* r, uint32_t a) {
    asm volatile("ldmatrix.sync.aligned.m8n8.x4.shared.b16 {%0,%1,%2,%3}, [%4];"
                 : "=r"(r[0]), "=r"(r[1]), "=r"(r[2]), "=r"(r[3]) : "r"(a));
}
__device__ __forceinline__ void ldsm4t(uint32_t* r, uint32_t a) {
    asm volatile("ldmatrix.sync.aligned.m8n8.x4.trans.shared.b16 {%0,%1,%2,%3}, [%4];"
                 : "=r"(r[0]), "=r"(r[1]), "=r"(r[2]), "=r"(r[3]) : "r"(a));
}
__device__ __forceinline__ void mma16(float* d, const uint32_t* a, uint32_t b0, uint32_t b1) {
    asm volatile("mma.sync.aligned.m16n8k16.row.col.f32.f16.f16.f32 "
                 "{%0,%1,%2,%3}, {%4,%5,%6,%7}, {%8,%9}, {%0,%1,%2,%3};"
                 : "+f"(d[0]), "+f"(d[1]), "+f"(d[2]), "+f"(d[3])
                 : "r"(a[0]), "r"(a[1]), "r"(a[2]), "r"(a[3]), "r"(b0), "r"(b1));
}
__device__ __forceinline__ void cpa16(uint32_t s, const void* g) {
    asm volatile("cp.async.cg.shared.global [%0], [%1], 16;" :: "r"(s), "l"(g));
}
__device__ __forceinline__ uint32_t pack2(float a, float b) {
    __half2 h = __floats2half2_rn(a, b);
    return *reinterpret_cast<uint32_t*>(&h);
}
#define CP_COMMIT() asm volatile("cp.async.commit_group;" ::: "memory")
#define CP_WAIT0()  asm volatile("cp.async.wait_group 0;" ::: "memory")
#define CP_WAIT1()  asm volatile("cp.async.wait_group 1;" ::: "memory")

// ================= kernel 1: mod = silu(temb) @ w_mod + b_mod =================
__global__ void k_mod(const float* __restrict__ temb, const float* __restrict__ w_mod,
                      const float* __restrict__ b_mod) {
    __shared__ float st[Dc];
    __shared__ float ps[4][64];
    int b = blockIdx.y;
    int tx = threadIdx.x & 63, ty = threadIdx.x >> 6;
    int j = blockIdx.x * 64 + tx;
    for (int i = threadIdx.x; i < Dc; i += 256) {
        float x = temb[b * Dc + i];
        st[i] = x / (1.f + __expf(-x));
    }
    __syncthreads();
    float acc = 0.f;
    int k0 = ty * 512;
#pragma unroll 4
    for (int i = 0; i < 512; i++)
        acc = fmaf(st[k0 + i], w_mod[(size_t)(k0 + i) * D3c + j], acc);
    ps[ty][tx] = acc;
    __syncthreads();
    if (ty == 0)
        g_mod[b * D3c + j] = ps[0][tx] + ps[1][tx] + ps[2][tx] + ps[3][tx] + b_mod[j];
}

// ====== kernel 2: xm = half(rmsnorm(x)*w_ln*(1+scale)+shift), float4 I/O ======
__global__ void k_rmsmod(const float* __restrict__ x, const float* __restrict__ w_ln) {
    int row = blockIdx.x;
    int b   = row >> 11;
    const float4* xr = (const float4*)(x + (size_t)row * Dc);
    int tid = threadIdx.x;

    float4 a0 = xr[tid], a1 = xr[tid + 256];
    float ss = a0.x*a0.x + a0.y*a0.y + a0.z*a0.z + a0.w*a0.w
             + a1.x*a1.x + a1.y*a1.y + a1.z*a1.z + a1.w*a1.w;
#pragma unroll
    for (int o = 16; o; o >>= 1) ss += __shfl_xor_sync(0xffffffffu, ss, o);
    __shared__ float red[8];
    __shared__ float sinv;
    if ((tid & 31) == 0) red[tid >> 5] = ss;
    __syncthreads();
    if (tid == 0) {
        float t = 0.f;
#pragma unroll
        for (int w = 0; w < 8; w++) t += red[w];
        sinv = rsqrtf(t * (1.f / Dc) + EPSc);
    }
    __syncthreads();
    float inv = sinv;
    const float4* shv = (const float4*)(g_mod + b * D3c);
    const float4* scv = shv + 512;
    const float4* wv  = (const float4*)w_ln;
    __half* xm = g_xmh + (size_t)row * Dc;
#pragma unroll
    for (int u = 0; u < 2; u++) {
        int i = tid + u * 256;
        float4 av = u ? a1 : a0;
        float4 w4 = wv[i], s4 = scv[i], h4 = shv[i];
        float o0 = fmaf(av.x * inv * w4.x, 1.f + s4.x, h4.x);
        float o1 = fmaf(av.y * inv * w4.y, 1.f + s4.y, h4.y);
        float o2 = fmaf(av.z * inv * w4.z, 1.f + s4.z, h4.z);
        float o3 = fmaf(av.w * inv * w4.w, 1.f + s4.w, h4.w);
        uint2 pk = make_uint2(pack2(o0, o1), pack2(o2, o3));
        *(uint2*)(xm + i * 4) = pk;
    }
}

// ====== batched transpose: all 4 weights in one launch ========================
__global__ void k_transpose4(const float* __restrict__ wq, const float* __restrict__ wk,
                             const float* __restrict__ wv, const float* __restrict__ wo) {
    __shared__ float t[32][33];
    const float* src; __half* dst; int N;
    switch (blockIdx.z) {
        case 0:  src = wq; dst = g_wTh;                         N = 2048; break;
        case 1:  src = wk; dst = g_wTh + (size_t)2048 * Dc;     N = 1024; break;
        case 2:  src = wv; dst = g_wTh + (size_t)3072 * Dc;     N = 1024; break;
        default: src = wo; dst = g_woTh;                        N = 2048; break;
    }
    int nb = blockIdx.x * 32;
    if (nb >= N) return;
    int kb = blockIdx.y * 32;
    int x = threadIdx.x, y = threadIdx.y;
#pragma unroll
    for (int i = 0; i < 32; i += 8)
        t[y + i][x] = src[(size_t)(kb + y + i) * N + nb + x];
    __syncthreads();
#pragma unroll
    for (int i = 0; i < 32; i += 8)
        dst[(size_t)(nb + y + i) * Dc + kb + x] = __float2half_rn(t[x][y + i]);
}

// ====== fp16 mma.sync GEMM: BM=128 BN=128 BK=64, 2 CTAs/SM =====================
// EPI=1: float out, +hidden + gate (O-projection).
// EPI=2: QKV epilogue — fused per-head RMSNorm + mixed RoPE via smem staging.
#define GSTAGE 36864
#define MMASMEM (GSTAGE * 3)         // 110592 bytes

template<int EPI>
__global__ void __launch_bounds__(256, 2)
k_mma(const __half* __restrict__ Ag, const __half* __restrict__ Bg,
      void* __restrict__ Cv, int N, int K, const float* __restrict__ hid,
      const float* __restrict__ cos1d = nullptr, const float* __restrict__ sin1d = nullptr,
      const float* __restrict__ rope3d = nullptr,
      const float* __restrict__ qn = nullptr, const float* __restrict__ kn = nullptr,
      const int* __restrict__ mp = nullptr) {
    extern __shared__ __half sh[];
    uint32_t base = smem_u32(sh);
    int t = threadIdx.x, l = t & 31, wid = t >> 5;
    int wm = wid >> 2, wn = wid & 3;
    int m0 = blockIdx.y * 128, n0 = blockIdx.x * 128;

    auto loadT = [&](int kt, int buf) {
        uint32_t ab = base + buf * GSTAGE;
#pragma unroll
        for (int i = 0; i < 4; i++) {
            int p = t + (i << 8); int r = p >> 3, c = p & 7;
            cpa16(ab + (r * 72 + c * 8) * 2,
                  Ag + (size_t)(m0 + r) * K + kt * 64 + c * 8);
        }
#pragma unroll
        for (int i = 0; i < 4; i++) {
            int p = t + (i << 8); int r = p >> 3, c = p & 7;
            cpa16(ab + 18432 + (r * 72 + c * 8) * 2,
                  Bg + (size_t)(n0 + r) * K + kt * 64 + c * 8);
        }
    };

    float acc[4][4][4];
#pragma unroll
    for (int i = 0; i < 4; i++)
#pragma unroll
        for (int j = 0; j < 4; j++)
#pragma unroll
            for (int c = 0; c < 4; c++) acc[i][j][c] = 0.f;

    int nk = K >> 6;
    loadT(0, 0); CP_COMMIT();
    loadT(1, 1); CP_COMMIT();

    int cur = 0;
    for (int kt = 0; kt < nk; kt++) {
        if (kt + 1 < nk) CP_WAIT1(); else CP_WAIT0();
        __syncthreads();
        if (kt + 2 < nk) {
            int nb = cur + 2; if (nb >= 3) nb -= 3;
            loadT(kt + 2, nb);
            CP_COMMIT();
        }

        uint32_t Ab = base + cur * GSTAGE;
        uint32_t Bb = Ab + 18432;
#pragma unroll
        for (int kc2 = 0; kc2 < 2; kc2++) {
            uint32_t bb[4][4];
#pragma unroll
            for (int j = 0; j < 4; j++)
                ldsm4(bb[j], Bb + ((wn * 32 + j * 8 + (l & 7)) * 72
                                   + (kc2 * 4 + (l >> 3)) * 8) * 2);
#pragma unroll
            for (int kc = 0; kc < 2; kc++) {
                uint32_t aa[4][4];
#pragma unroll
                for (int i = 0; i < 4; i++)
                    ldsm4(aa[i], Ab + ((wm * 64 + i * 16 + ((l >> 3) & 1) * 8 + (l & 7)) * 72
                                       + (kc2 * 4 + 2 * kc + (l >> 4)) * 8) * 2);
#pragma unroll
                for (int i = 0; i < 4; i++)
#pragma unroll
                    for (int j = 0; j < 4; j++)
                        mma16(acc[i][j], aa[i], bb[j][2 * kc], bb[j][2 * kc + 1]);
            }
        }
        cur++; if (cur == 3) cur = 0;
    }

    if (EPI == 1) {
#pragma unroll
        for (int i = 0; i < 4; i++) {
            int gm = m0 + wm * 64 + i * 16 + (l >> 2);
#pragma unroll
            for (int j = 0; j < 4; j++) {
                int gn = n0 + wn * 32 + j * 8 + 2 * (l & 3);
                float* C = (float*)Cv;
                size_t o0 = (size_t)gm * N + gn;
                size_t o1 = (size_t)(gm + 8) * N + gn;
                int b0 = gm >> 11, b1 = (gm + 8) >> 11;
                float2 h0 = *(const float2*)(hid + o0);
                float2 h1 = *(const float2*)(hid + o1);
                float2 g0 = *(const float2*)(g_mod + b0 * D3c + 2 * Dc + gn);
                float2 g1 = *(const float2*)(g_mod + b1 * D3c + 2 * Dc + gn);
                *(float2*)(C + o0) = make_float2(fmaf(g0.x, acc[i][j][0], h0.x),
                                                 fmaf(g0.y, acc[i][j][1], h0.y));
                *(float2*)(C + o1) = make_float2(fmaf(g1.x, acc[i][j][2], h1.x),
                                                 fmaf(g1.y, acc[i][j][3], h1.y));
            }
        }
        return;
    }

    // ---------- EPI == 2: stage tile to smem, fused qknorm + rope ----------
    __syncthreads();                       // mainloop smem reads complete
    float* S = (float*)sh;                 // [128][132] fp32, 67584 B
#pragma unroll
    for (int i = 0; i < 4; i++) {
        int rl = wm * 64 + i * 16 + (l >> 2);
#pragma unroll
        for (int j = 0; j < 4; j++) {
            int cl = wn * 32 + j * 8 + 2 * (l & 3);
            *(float2*)&S[rl * 132 + cl]       = make_float2(acc[i][j][0], acc[i][j][1]);
            *(float2*)&S[(rl + 8) * 132 + cl] = make_float2(acc[i][j][2], acc[i][j][3]);
        }
    }
    __syncthreads();

    int head = n0 >> 7;                    // 0..15 q | 16..23 k | 24..31 v
    int d0 = l * 4;
    __half* C = (__half*)Cv;

    for (int rr = 0; rr < 16; rr++) {
        int r  = wid * 16 + rr;
        int gm = m0 + r;
        int b  = gm >> 11, ll = gm & 2047;
        float4 v4 = *(const float4*)&S[r * 132 + d0];
        float val[4] = {v4.x, v4.y, v4.z, v4.w};
        float out[4];

        if (head >= 24) {                  // V: passthrough
            out[0] = val[0]; out[1] = val[1]; out[2] = val[2]; out[3] = val[3];
        } else {
            const float* w = (head < 16) ? qn : kn;
            float ss = 0.f;
#pragma unroll
            for (int i = 0; i < 4; i++) ss = fmaf(val[i], val[i], ss);
#pragma unroll
            for (int o = 16; o; o >>= 1) ss += __shfl_xor_sync(0xffffffffu, ss, o);
            float inv = rsqrtf(ss * (1.f / Dhc) + EPSc);
            float4 wv4 = *(const float4*)(w + d0);
            val[0] *= inv * wv4.x; val[1] *= inv * wv4.y;
            val[2] *= inv * wv4.z; val[3] *= inv * wv4.w;

            bool is64 = (mp[1] == 0);
            bool in_full = false, in_img = false; int rel = 0;
#pragma unroll
            for (int m = 0; m < 2; m++) {
                int off, ln;
                if (is64) { off = mp[(b * 4 + m * 2) * 2]; ln = mp[(b * 4 + m * 2 + 1) * 2]; }
                else      { off = mp[b * 4 + m * 2];       ln = mp[b * 4 + m * 2 + 1]; }
                int seg_end = off + max(ln, 1);
                if (ll >= off && ll < seg_end) in_full = true;
                if (ll >= off + 1 && ll < off + ln) { in_img = true; rel += ll - (off + 1); }
            }
            bool text = !in_full;
            bool img  = in_img && (rel < 1024);
            rel = min(max(rel, 0), 1023);

            if (text) {
                float4 c4 = *(const float4*)(cos1d + ll * Dhc + d0);
                float4 s4 = *(const float4*)(sin1d + ll * Dhc + d0);
                float sgn = (d0 < 64) ? -1.f : 1.f;
                float cc[4] = {c4.x, c4.y, c4.z, c4.w};
                float s_[4] = {s4.x, s4.y, s4.z, s4.w};
#pragma unroll
                for (int i = 0; i < 4; i++) {
                    float partner = __shfl_xor_sync(0xffffffffu, val[i], 16);
                    out[i] = fmaf(val[i], cc[i], sgn * partner * s_[i]);
                }
            } else {
                const float4 R0 = *(const float4*)(rope3d + ((size_t)rel * 64 + 2 * l) * 4);
                const float4 R1 = *(const float4*)(rope3d + ((size_t)rel * 64 + 2 * l + 1) * 4);
                float o0 = fmaf(val[0], R0.x, val[1] * R0.z);
                float o1 = fmaf(val[0], R0.y, val[1] * R0.w);
                float o2 = fmaf(val[2], R1.x, val[3] * R1.z);
                float o3 = fmaf(val[2], R1.y, val[3] * R1.w);
                out[0] = img ? o0 : val[0]; out[1] = img ? o1 : val[1];
                out[2] = img ? o2 : val[2]; out[3] = img ? o3 : val[3];
            }
        }
        uint2 pk = make_uint2(pack2(out[0], out[1]), pack2(out[2], out[3]));
        *(uint2*)(C + (size_t)gm * N + n0 + d0) = pk;
    }
}

// ====== flash attention, FA2-style (round-13 exact, verified) =================
#define FSMEM (43520 * 2)   // 87040 bytes, 2 CTAs/SM

__global__ void __launch_bounds__(128)
k_flash(__half* __restrict__ go) {
    extern __shared__ __half fh[];
    uint32_t base = smem_u32(fh);

    int t = threadIdx.x, l = t & 31, wid = t >> 5;
    int lo = l & 3, lr = l >> 2;
    int q0 = blockIdx.x << 6;
    int h  = blockIdx.y, b = blockIdx.z;
    int kh = h >> 1;
    const float SC = 0.08838834764831845f;

    const __half* qkv = g_qkvh;

#pragma unroll
    for (int i = 0; i < 8; i++) {
        int p = t + (i << 7); int r = p >> 4, c = p & 15;
        cpa16(base + (r * 136 + c * 8) * 2,
              qkv + (size_t)(b * Lc + q0 + r) * QKVN + h * Dhc + c * 8);
    }
    auto loadKV = [&](int kt, int buf) {
        uint32_t sb = base + (8704 + buf * 17408) * 2;
#pragma unroll
        for (int i = 0; i < 8; i++) {
            int p = t + (i << 7); int r = p >> 4, c = p & 15;
            cpa16(sb + (r * 136 + c * 8) * 2,
                  qkv + (size_t)(b * Lc + kt * 64 + r) * QKVN + 2048 + kh * Dhc + c * 8);
        }
#pragma unroll
        for (int i = 0; i < 8; i++) {
            int p = t + (i << 7); int r = p >> 4, c = p & 15;
            cpa16(sb + (8704 + r * 136 + c * 8) * 2,
                  qkv + (size_t)(b * Lc + kt * 64 + r) * QKVN + 3072 + kh * Dhc + c * 8);
        }
    };
    loadKV(0, 0); CP_COMMIT();
    loadKV(1, 1); CP_COMMIT();
    CP_WAIT1();
    __syncthreads();

    uint32_t Qa[8][4];
#pragma unroll
    for (int kq = 0; kq < 8; kq++)
        ldsm4(Qa[kq], base + ((wid * 16 + ((l >> 3) & 1) * 8 + (l & 7)) * 136
                              + (kq * 2 + (l >> 4)) * 8) * 2);

    float accO[16][4];
    float m_run[2], l_run[2];
#pragma unroll
    for (int j = 0; j < 16; j++)
#pragma unroll
        for (int c = 0; c < 4; c++) accO[j][c] = 0.f;
    m_run[0] = m_run[1] = -1e30f;
    l_run[0] = l_run[1] = 0.f;

    for (int kt = 0; kt < 32; kt++) {
        int cur = kt & 1;
        uint32_t Kb = base + (8704 + cur * 17408) * 2;
        uint32_t Vb = Kb + 8704 * 2;

        float accS[8][4];
#pragma unroll
        for (int j = 0; j < 8; j++)
#pragma unroll
            for (int c = 0; c < 4; c++) accS[j][c] = 0.f;
#pragma unroll
        for (int kc2 = 0; kc2 < 4; kc2++) {
            uint32_t bb[8][4];
#pragma unroll
            for (int nj = 0; nj < 8; nj++)
                ldsm4(bb[nj], Kb + ((nj * 8 + (l & 7)) * 136 + (kc2 * 4 + (l >> 3)) * 8) * 2);
#pragma unroll
            for (int kc = 0; kc < 2; kc++)
#pragma unroll
                for (int nj = 0; nj < 8; nj++)
                    mma16(accS[nj], Qa[kc2 * 2 + kc], bb[nj][2 * kc], bb[nj][2 * kc + 1]);
        }

        float pm[2], ps[2];
        pm[0] = pm[1] = -1e30f; ps[0] = ps[1] = 0.f;
#pragma unroll
        for (int nj = 0; nj < 8; nj++)
#pragma unroll
            for (int c = 0; c < 4; c++) {
                float v = accS[nj][c] * SC;
                accS[nj][c] = v;
                pm[c >> 1] = fmaxf(pm[c >> 1], v);
            }
#pragma unroll
        for (int r = 0; r < 2; r++) {
            pm[r] = fmaxf(pm[r], __shfl_xor_sync(0xffffffffu, pm[r], 1));
            pm[r] = fmaxf(pm[r], __shfl_xor_sync(0xffffffffu, pm[r], 2));
        }
#pragma unroll
        for (int nj = 0; nj < 8; nj++)
#pragma unroll
            for (int c = 0; c < 4; c++) {
                float p = __expf(accS[nj][c] - pm[c >> 1]);
                accS[nj][c] = p;
                ps[c >> 1] += p;
            }
#pragma unroll
        for (int r = 0; r < 2; r++) {
            ps[r] += __shfl_xor_sync(0xffffffffu, ps[r], 1);
            ps[r] += __shfl_xor_sync(0xffffffffu, ps[r], 2);
        }
        float cf[2], corr[2];
#pragma unroll
        for (int r = 0; r < 2; r++) {
            float mnew = fmaxf(m_run[r], pm[r]);
            corr[r] = __expf(m_run[r] - mnew);
            cf[r]   = __expf(pm[r] - mnew);
            l_run[r] = l_run[r] * corr[r] + ps[r] * cf[r];
            m_run[r] = mnew;
        }
#pragma unroll
        for (int nj = 0; nj < 16; nj++)
#pragma unroll
            for (int c = 0; c < 4; c++)
                accO[nj][c] *= corr[c >> 1];

        uint32_t Pa[4][4];
#pragma unroll
        for (int kc = 0; kc < 4; kc++) {
            Pa[kc][0] = pack2(accS[2*kc][0]   * cf[0], accS[2*kc][1]   * cf[0]);
            Pa[kc][1] = pack2(accS[2*kc][2]   * cf[1], accS[2*kc][3]   * cf[1]);
            Pa[kc][2] = pack2(accS[2*kc+1][0] * cf[0], accS[2*kc+1][1] * cf[0]);
            Pa[kc][3] = pack2(accS[2*kc+1][2] * cf[1], accS[2*kc+1][3] * cf[1]);
        }

#pragma unroll
        for (int kc2 = 0; kc2 < 2; kc2++)
#pragma unroll
            for (int nh = 0; nh < 2; nh++) {
                uint32_t bb[8][4];
#pragma unroll
                for (int nj = 0; nj < 8; nj++)
                    ldsm4t(bb[nj], Vb + ((kc2 * 32 + (l >> 3) * 8 + (l & 7)) * 136
                                         + (nh * 8 + nj) * 8) * 2);
#pragma unroll
                for (int kc = 0; kc < 2; kc++)
#pragma unroll
                    for (int nj = 0; nj < 8; nj++)
                        mma16(accO[nh * 8 + nj], Pa[kc2 * 2 + kc],
                              bb[nj][2 * kc], bb[nj][2 * kc + 1]);
            }

        if (kt < 31) {
            CP_WAIT0();
            __syncthreads();
            if (kt < 30) { loadKV(kt + 2, cur); CP_COMMIT(); }
        }
    }

    float inv0 = 1.f / l_run[0], inv1 = 1.f / l_run[1];
    int row0 = q0 + wid * 16 + lr;
#pragma unroll
    for (int nj = 0; nj < 16; nj++) {
        int col = h * Dhc + nj * 8 + 2 * lo;
        *(__half2*)(go + (size_t)(b * Lc + row0) * Dc + col) =
            __floats2half2_rn(accO[nj][0] * inv0, accO[nj][1] * inv0);
        *(__half2*)(go + (size_t)(b * Lc + row0 + 8) * Dc + col) =
            __floats2half2_rn(accO[nj][2] * inv1, accO[nj][3] * inv1);
    }
}

// ================================ host ========================================
extern "C" void kernel_launch(void* const* d_in, const int* in_sizes, int n_in,
                              void* d_out, int out_size) {
    const float* hidden = (const float*)d_in[0];
    const float* temb   = (const float*)d_in[1];
    const float* w_ln   = (const float*)d_in[2];
    const float* w_mod  = (const float*)d_in[3];
    const float* b_mod  = (const float*)d_in[4];
    const float* wq     = (const float*)d_in[5];
    const float* wk     = (const float*)d_in[6];
    const float* wv     = (const float*)d_in[7];
    const float* wo     = (const float*)d_in[8];
    const float* qn     = (const float*)d_in[9];
    const float* kn     = (const float*)d_in[10];
    const float* cos1   = (const float*)d_in[11];
    const float* sin1   = (const float*)d_in[12];
    const float* rope3  = (const float*)d_in[13];
    const int*   mpos   = (const int*)d_in[14];
    float* out = (float*)d_out;

    void *pxm, *pqkv, *po, *pwT, *pwoT;
    cudaGetSymbolAddress(&pxm,  g_xmh);
    cudaGetSymbolAddress(&pqkv, g_qkvh);
    cudaGetSymbolAddress(&po,   g_oh);
    cudaGetSymbolAddress(&pwT,  g_wTh);
    cudaGetSymbolAddress(&pwoT, g_woTh);

    cudaFuncSetAttribute(k_mma<1>, cudaFuncAttributeMaxDynamicSharedMemorySize, MMASMEM);
    cudaFuncSetAttribute(k_mma<2>, cudaFuncAttributeMaxDynamicSharedMemorySize, MMASMEM);
    cudaFuncSetAttribute(k_flash, cudaFuncAttributeMaxDynamicSharedMemorySize, FSMEM);

    k_mod<<<dim3(D3c / 64, Bc), 256>>>(temb, w_mod, b_mod);
    k_rmsmod<<<Bc * Lc, 256>>>(hidden, w_ln);

    k_transpose4<<<dim3(64, 64, 4), dim3(32, 8)>>>(wq, wk, wv, wo);

    // fused QKV GEMM + per-head RMSNorm + mixed RoPE epilogue (half out)
    k_mma<2><<<dim3(QKVN / 128, (Bc * Lc) / 128), 256, MMASMEM>>>(
        (const __half*)pxm, (const __half*)pwT, pqkv, QKVN, Dc, nullptr,
        cos1, sin1, rope3, qn, kn, mpos);

    k_flash<<<dim3(Lc / 64, Hc, Bc), 128, FSMEM>>>((__half*)po);

    // output projection + residual/gate epilogue (float out)
    k_mma<1><<<dim3(Dc / 128, (Bc * Lc) / 128), 256, MMASMEM>>>(
        (const __half*)po, (const __half*)pwoT, out, Dc, Dc, hidden);
}

// round 17
// speedup vs baseline: 1.0283x; 1.0014x over previous
#include <cuda_runtime.h>
#include <cuda_fp16.h>
#include <cstdint>

#define Bc   2
#define Lc   2048
#define Dc   2048
#define Hc   16
#define KVHc 8
#define Dhc  128
#define QKVN 4096
#define D3c  6144
#define EPSc 1e-5f

// ---------------- scratch (device globals: allocation-guard safe) -------------
__device__ float  g_mod [Bc * D3c];
__device__ __half g_xmh [(size_t)Bc * Lc * Dc];
__device__ __half g_qkvh[(size_t)Bc * Lc * QKVN];  // 0..2047 Q | 2048..3071 K | 3072..4095 V
__device__ __half g_oh  [(size_t)Bc * Lc * Dc];
__device__ __half g_wTh [(size_t)QKVN * Dc];
__device__ __half g_woTh[(size_t)Dc * Dc];

// ================= helpers ====================================================
__device__ __forceinline__ uint32_t smem_u32(const void* p) {
    uint32_t a;
    asm("{ .reg .u64 t; cvta.to.shared.u64 t, %1; cvt.u32.u64 %0, t; }" : "=r"(a) : "l"(p));
    return a;
}
__device__ __forceinline__ void ldsm4(uint32_t* r, uint32_t a) {
    asm volatile("ldmatrix.sync.aligned.m8n8.x4.shared.b16 {%0,%1,%2,%3}, [%4];"
                 : "=r"(r[0]), "=r"(r[1]), "=r"(r[2]), "=r"(r[3]) : "r"(a));
}
__device__ __forceinline__ void ldsm4t(uint32_t* r, uint32_t a) {
    asm volatile("ldmatrix.sync.aligned.m8n8.x4.trans.shared.b16 {%0,%1,%2,%3}, [%4];"
                 : "=r"(r[0]), "=r"(r[1]), "=r"(r[2]), "=r"(r[3]) : "r"(a));
}
__device__ __forceinline__ void mma16(float* d, const uint32_t* a, uint32_t b0, uint32_t b1) {
    asm volatile("mma.sync.aligned.m16n8k16.row.col.f32.f16.f16.f32 "
                 "{%0,%1,%2,%3}, {%4,%5,%6,%7}, {%8,%9}, {%0,%1,%2,%3};"
                 : "+f"(d[0]), "+f"(d[1]), "+f"(d[2]), "+f"(d[3])
                 : "r"(a[0]), "r"(a[1]), "r"(a[2]), "r"(a[3]), "r"(b0), "r"(b1));
}
__device__ __forceinline__ void cpa16(uint32_t s, const void* g) {
    asm volatile("cp.async.cg.shared.global [%0], [%1], 16;" :: "r"(s), "l"(g));
}
__device__ __forceinline__ uint32_t pack2(float a, float b) {
    __half2 h = __floats2half2_rn(a, b);
    return *reinterpret_cast<uint32_t*>(&h);
}
__device__ __forceinline__ float ex2(float x) {
    float r; asm("ex2.approx.f32 %0, %1;" : "=f"(r) : "f"(x));
    return r;
}
#define CP_COMMIT() asm volatile("cp.async.commit_group;" ::: "memory")
#define CP_WAIT0()  asm volatile("cp.async.wait_group 0;" ::: "memory")
#define CP_WAIT1()  asm volatile("cp.async.wait_group 1;" ::: "memory")

// ================= kernel 1: mod = silu(temb) @ w_mod + b_mod =================
__global__ void k_mod(const float* __restrict__ temb, const float* __restrict__ w_mod,
                      const float* __restrict__ b_mod) {
    __shared__ float st[Dc];
    __shared__ float ps[4][64];
    int b = blockIdx.y;
    int tx = threadIdx.x & 63, ty = threadIdx.x >> 6;
    int j = blockIdx.x * 64 + tx;
    for (int i = threadIdx.x; i < Dc; i += 256) {
        float x = temb[b * Dc + i];
        st[i] = x / (1.f + __expf(-x));
    }
    __syncthreads();
    float acc = 0.f;
    int k0 = ty * 512;
#pragma unroll 4
    for (int i = 0; i < 512; i++)
        acc = fmaf(st[k0 + i], w_mod[(size_t)(k0 + i) * D3c + j], acc);
    ps[ty][tx] = acc;
    __syncthreads();
    if (ty == 0)
        g_mod[b * D3c + j] = ps[0][tx] + ps[1][tx] + ps[2][tx] + ps[3][tx] + b_mod[j];
}

// ====== kernel 2: xm = half(rmsnorm(x)*w_ln*(1+scale)+shift), float4 I/O ======
__global__ void k_rmsmod(const float* __restrict__ x, const float* __restrict__ w_ln) {
    int row = blockIdx.x;
    int b   = row >> 11;
    const float4* xr = (const float4*)(x + (size_t)row * Dc);
    int tid = threadIdx.x;

    float4 a0 = xr[tid], a1 = xr[tid + 256];
    float ss = a0.x*a0.x + a0.y*a0.y + a0.z*a0.z + a0.w*a0.w
             + a1.x*a1.x + a1.y*a1.y + a1.z*a1.z + a1.w*a1.w;
#pragma unroll
    for (int o = 16; o; o >>= 1) ss += __shfl_xor_sync(0xffffffffu, ss, o);
    __shared__ float red[8];
    __shared__ float sinv;
    if ((tid & 31) == 0) red[tid >> 5] = ss;
    __syncthreads();
    if (tid == 0) {
        float t = 0.f;
#pragma unroll
        for (int w = 0; w < 8; w++) t += red[w];
        sinv = rsqrtf(t * (1.f / Dc) + EPSc);
    }
    __syncthreads();
    float inv = sinv;
    const float4* shv = (const float4*)(g_mod + b * D3c);
    const float4* scv = shv + 512;
    const float4* wv  = (const float4*)w_ln;
    __half* xm = g_xmh + (size_t)row * Dc;
#pragma unroll
    for (int u = 0; u < 2; u++) {
        int i = tid + u * 256;
        float4 av = u ? a1 : a0;
        float4 w4 = wv[i], s4 = scv[i], h4 = shv[i];
        float o0 = fmaf(av.x * inv * w4.x, 1.f + s4.x, h4.x);
        float o1 = fmaf(av.y * inv * w4.y, 1.f + s4.y, h4.y);
        float o2 = fmaf(av.z * inv * w4.z, 1.f + s4.z, h4.z);
        float o3 = fmaf(av.w * inv * w4.w, 1.f + s4.w, h4.w);
        uint2 pk = make_uint2(pack2(o0, o1), pack2(o2, o3));
        *(uint2*)(xm + i * 4) = pk;
    }
}

// ====== batched transpose: all 4 weights in one launch ========================
__global__ void k_transpose4(const float* __restrict__ wq, const float* __restrict__ wk,
                             const float* __restrict__ wv, const float* __restrict__ wo) {
    __shared__ float t[32][33];
    const float* src; __half* dst; int N;
    switch (blockIdx.z) {
        case 0:  src = wq; dst = g_wTh;                         N = 2048; break;
        case 1:  src = wk; dst = g_wTh + (size_t)2048 * Dc;     N = 1024; break;
        case 2:  src = wv; dst = g_wTh + (size_t)3072 * Dc;     N = 1024; break;
        default: src = wo; dst = g_woTh;                        N = 2048; break;
    }
    int nb = blockIdx.x * 32;
    if (nb >= N) return;
    int kb = blockIdx.y * 32;
    int x = threadIdx.x, y = threadIdx.y;
#pragma unroll
    for (int i = 0; i < 32; i += 8)
        t[y + i][x] = src[(size_t)(kb + y + i) * N + nb + x];
    __syncthreads();
#pragma unroll
    for (int i = 0; i < 32; i += 8)
        dst[(size_t)(nb + y + i) * Dc + kb + x] = __float2half_rn(t[x][y + i]);
}

// ====== fp16 mma.sync GEMM: BM=128 BN=128 BK=64, 2 CTAs/SM =====================
// EPI=1: float out, +hidden + gate (O-projection).
// EPI=2: QKV epilogue — fused per-head RMSNorm + mixed RoPE via smem staging.
#define GSTAGE 36864
#define MMASMEM (GSTAGE * 3)         // 110592 bytes

template<int EPI>
__global__ void __launch_bounds__(256, 2)
k_mma(const __half* __restrict__ Ag, const __half* __restrict__ Bg,
      void* __restrict__ Cv, int N, int K, const float* __restrict__ hid,
      const float* __restrict__ cos1d = nullptr, const float* __restrict__ sin1d = nullptr,
      const float* __restrict__ rope3d = nullptr,
      const float* __restrict__ qn = nullptr, const float* __restrict__ kn = nullptr,
      const int* __restrict__ mp = nullptr) {
    extern __shared__ __half sh[];
    uint32_t base = smem_u32(sh);
    int t = threadIdx.x, l = t & 31, wid = t >> 5;
    int wm = wid >> 2, wn = wid & 3;
    int m0 = blockIdx.y * 128, n0 = blockIdx.x * 128;

    auto loadT = [&](int kt, int buf) {
        uint32_t ab = base + buf * GSTAGE;
#pragma unroll
        for (int i = 0; i < 4; i++) {
            int p = t + (i << 8); int r = p >> 3, c = p & 7;
            cpa16(ab + (r * 72 + c * 8) * 2,
                  Ag + (size_t)(m0 + r) * K + kt * 64 + c * 8);
        }
#pragma unroll
        for (int i = 0; i < 4; i++) {
            int p = t + (i << 8); int r = p >> 3, c = p & 7;
            cpa16(ab + 18432 + (r * 72 + c * 8) * 2,
                  Bg + (size_t)(n0 + r) * K + kt * 64 + c * 8);
        }
    };

    float acc[4][4][4];
#pragma unroll
    for (int i = 0; i < 4; i++)
#pragma unroll
        for (int j = 0; j < 4; j++)
#pragma unroll
            for (int c = 0; c < 4; c++) acc[i][j][c] = 0.f;

    int nk = K >> 6;
    loadT(0, 0); CP_COMMIT();
    loadT(1, 1); CP_COMMIT();

    int cur = 0;
    for (int kt = 0; kt < nk; kt++) {
        if (kt + 1 < nk) CP_WAIT1(); else CP_WAIT0();
        __syncthreads();
        if (kt + 2 < nk) {
            int nb = cur + 2; if (nb >= 3) nb -= 3;
            loadT(kt + 2, nb);
            CP_COMMIT();
        }

        uint32_t Ab = base + cur * GSTAGE;
        uint32_t Bb = Ab + 18432;
#pragma unroll
        for (int kc2 = 0; kc2 < 2; kc2++) {
            uint32_t bb[4][4];
#pragma unroll
            for (int j = 0; j < 4; j++)
                ldsm4(bb[j], Bb + ((wn * 32 + j * 8 + (l & 7)) * 72
                                   + (kc2 * 4 + (l >> 3)) * 8) * 2);
#pragma unroll
            for (int kc = 0; kc < 2; kc++) {
                uint32_t aa[4][4];
#pragma unroll
                for (int i = 0; i < 4; i++)
                    ldsm4(aa[i], Ab + ((wm * 64 + i * 16 + ((l >> 3) & 1) * 8 + (l & 7)) * 72
                                       + (kc2 * 4 + 2 * kc + (l >> 4)) * 8) * 2);
#pragma unroll
                for (int i = 0; i < 4; i++)
#pragma unroll
                    for (int j = 0; j < 4; j++)
                        mma16(acc[i][j], aa[i], bb[j][2 * kc], bb[j][2 * kc + 1]);
            }
        }
        cur++; if (cur == 3) cur = 0;
    }

    if (EPI == 1) {
#pragma unroll
        for (int i = 0; i < 4; i++) {
            int gm = m0 + wm * 64 + i * 16 + (l >> 2);
#pragma unroll
            for (int j = 0; j < 4; j++) {
                int gn = n0 + wn * 32 + j * 8 + 2 * (l & 3);
                float* C = (float*)Cv;
                size_t o0 = (size_t)gm * N + gn;
                size_t o1 = (size_t)(gm + 8) * N + gn;
                int b0 = gm >> 11, b1 = (gm + 8) >> 11;
                float2 h0 = *(const float2*)(hid + o0);
                float2 h1 = *(const float2*)(hid + o1);
                float2 g0 = *(const float2*)(g_mod + b0 * D3c + 2 * Dc + gn);
                float2 g1 = *(const float2*)(g_mod + b1 * D3c + 2 * Dc + gn);
                *(float2*)(C + o0) = make_float2(fmaf(g0.x, acc[i][j][0], h0.x),
                                                 fmaf(g0.y, acc[i][j][1], h0.y));
                *(float2*)(C + o1) = make_float2(fmaf(g1.x, acc[i][j][2], h1.x),
                                                 fmaf(g1.y, acc[i][j][3], h1.y));
            }
        }
        return;
    }

    // ---------- EPI == 2: stage tile to smem, fused qknorm + rope ----------
    __syncthreads();
    float* S = (float*)sh;                 // [128][132] fp32
#pragma unroll
    for (int i = 0; i < 4; i++) {
        int rl = wm * 64 + i * 16 + (l >> 2);
#pragma unroll
        for (int j = 0; j < 4; j++) {
            int cl = wn * 32 + j * 8 + 2 * (l & 3);
            *(float2*)&S[rl * 132 + cl]       = make_float2(acc[i][j][0], acc[i][j][1]);
            *(float2*)&S[(rl + 8) * 132 + cl] = make_float2(acc[i][j][2], acc[i][j][3]);
        }
    }
    __syncthreads();

    int head = n0 >> 7;
    int d0 = l * 4;
    __half* C = (__half*)Cv;

    for (int rr = 0; rr < 16; rr++) {
        int r  = wid * 16 + rr;
        int gm = m0 + r;
        int b  = gm >> 11, ll = gm & 2047;
        float4 v4 = *(const float4*)&S[r * 132 + d0];
        float val[4] = {v4.x, v4.y, v4.z, v4.w};
        float out[4];

        if (head >= 24) {
            out[0] = val[0]; out[1] = val[1]; out[2] = val[2]; out[3] = val[3];
        } else {
            const float* w = (head < 16) ? qn : kn;
            float ss = 0.f;
#pragma unroll
            for (int i = 0; i < 4; i++) ss = fmaf(val[i], val[i], ss);
#pragma unroll
            for (int o = 16; o; o >>= 1) ss += __shfl_xor_sync(0xffffffffu, ss, o);
            float inv = rsqrtf(ss * (1.f / Dhc) + EPSc);
            float4 wv4 = *(const float4*)(w + d0);
            val[0] *= inv * wv4.x; val[1] *= inv * wv4.y;
            val[2] *= inv * wv4.z; val[3] *= inv * wv4.w;

            bool is64 = (mp[1] == 0);
            bool in_full = false, in_img = false; int rel = 0;
#pragma unroll
            for (int m = 0; m < 2; m++) {
                int off, ln;
                if (is64) { off = mp[(b * 4 + m * 2) * 2]; ln = mp[(b * 4 + m * 2 + 1) * 2]; }
                else      { off = mp[b * 4 + m * 2];       ln = mp[b * 4 + m * 2 + 1]; }
                int seg_end = off + max(ln, 1);
                if (ll >= off && ll < seg_end) in_full = true;
                if (ll >= off + 1 && ll < off + ln) { in_img = true; rel += ll - (off + 1); }
            }
            bool text = !in_full;
            bool img  = in_img && (rel < 1024);
            rel = min(max(rel, 0), 1023);

            if (text) {
                float4 c4 = *(const float4*)(cos1d + ll * Dhc + d0);
                float4 s4 = *(const float4*)(sin1d + ll * Dhc + d0);
                float sgn = (d0 < 64) ? -1.f : 1.f;
                float cc[4] = {c4.x, c4.y, c4.z, c4.w};
                float s_[4] = {s4.x, s4.y, s4.z, s4.w};
#pragma unroll
                for (int i = 0; i < 4; i++) {
                    float partner = __shfl_xor_sync(0xffffffffu, val[i], 16);
                    out[i] = fmaf(val[i], cc[i], sgn * partner * s_[i]);
                }
            } else {
                const float4 R0 = *(const float4*)(rope3d + ((size_t)rel * 64 + 2 * l) * 4);
                const float4 R1 = *(const float4*)(rope3d + ((size_t)rel * 64 + 2 * l + 1) * 4);
                float o0 = fmaf(val[0], R0.x, val[1] * R0.z);
                float o1 = fmaf(val[0], R0.y, val[1] * R0.w);
                float o2 = fmaf(val[2], R1.x, val[3] * R1.z);
                float o3 = fmaf(val[2], R1.y, val[3] * R1.w);
                out[0] = img ? o0 : val[0]; out[1] = img ? o1 : val[1];
                out[2] = img ? o2 : val[2]; out[3] = img ? o3 : val[3];
            }
        }
        uint2 pk = make_uint2(pack2(out[0], out[1]), pack2(out[2], out[3]));
        *(uint2*)(C + (size_t)gm * N + n0 + d0) = pk;
    }
}

// ====== flash attention, FA2-style; softmax in exp2 domain ====================
#define FSMEM (43520 * 2)   // 87040 bytes, 2 CTAs/SM

__global__ void __launch_bounds__(128)
k_flash(__half* __restrict__ go) {
    extern __shared__ __half fh[];
    uint32_t base = smem_u32(fh);

    int t = threadIdx.x, l = t & 31, wid = t >> 5;
    int lo = l & 3, lr = l >> 2;
    int q0 = blockIdx.x << 6;
    int h  = blockIdx.y, b = blockIdx.z;
    int kh = h >> 1;
    const float SC2 = 0.08838834764831845f * 1.4426950408889634f;  // /sqrt(128)*log2(e)

    const __half* qkv = g_qkvh;

#pragma unroll
    for (int i = 0; i < 8; i++) {
        int p = t + (i << 7); int r = p >> 4, c = p & 15;
        cpa16(base + (r * 136 + c * 8) * 2,
              qkv + (size_t)(b * Lc + q0 + r) * QKVN + h * Dhc + c * 8);
    }
    auto loadKV = [&](int kt, int buf) {
        uint32_t sb = base + (8704 + buf * 17408) * 2;
#pragma unroll
        for (int i = 0; i < 8; i++) {
            int p = t + (i << 7); int r = p >> 4, c = p & 15;
            cpa16(sb + (r * 136 + c * 8) * 2,
                  qkv + (size_t)(b * Lc + kt * 64 + r) * QKVN + 2048 + kh * Dhc + c * 8);
        }
#pragma unroll
        for (int i = 0; i < 8; i++) {
            int p = t + (i << 7); int r = p >> 4, c = p & 15;
            cpa16(sb + (8704 + r * 136 + c * 8) * 2,
                  qkv + (size_t)(b * Lc + kt * 64 + r) * QKVN + 3072 + kh * Dhc + c * 8);
        }
    };
    loadKV(0, 0); CP_COMMIT();
    loadKV(1, 1); CP_COMMIT();
    CP_WAIT1();
    __syncthreads();

    uint32_t Qa[8][4];
#pragma unroll
    for (int kq = 0; kq < 8; kq++)
        ldsm4(Qa[kq], base + ((wid * 16 + ((l >> 3) & 1) * 8 + (l & 7)) * 136
                              + (kq * 2 + (l >> 4)) * 8) * 2);

    float accO[16][4];
    float m_run[2], l_run[2];
#pragma unroll
    for (int j = 0; j < 16; j++)
#pragma unroll
        for (int c = 0; c < 4; c++) accO[j][c] = 0.f;
    m_run[0] = m_run[1] = -1e30f;
    l_run[0] = l_run[1] = 0.f;

    for (int kt = 0; kt < 32; kt++) {
        int cur = kt & 1;
        uint32_t Kb = base + (8704 + cur * 17408) * 2;
        uint32_t Vb = Kb + 8704 * 2;

        float accS[8][4];
#pragma unroll
        for (int j = 0; j < 8; j++)
#pragma unroll
            for (int c = 0; c < 4; c++) accS[j][c] = 0.f;
#pragma unroll
        for (int kc2 = 0; kc2 < 4; kc2++) {
            uint32_t bb[8][4];
#pragma unroll
            for (int nj = 0; nj < 8; nj++)
                ldsm4(bb[nj], Kb + ((nj * 8 + (l & 7)) * 136 + (kc2 * 4 + (l >> 3)) * 8) * 2);
#pragma unroll
            for (int kc = 0; kc < 2; kc++)
#pragma unroll
                for (int nj = 0; nj < 8; nj++)
                    mma16(accS[nj], Qa[kc2 * 2 + kc], bb[nj][2 * kc], bb[nj][2 * kc + 1]);
        }

        // softmax in exp2 domain: scores scaled by SC*log2(e)
        float pm[2], ps[2];
        pm[0] = pm[1] = -1e30f; ps[0] = ps[1] = 0.f;
#pragma unroll
        for (int nj = 0; nj < 8; nj++)
#pragma unroll
            for (int c = 0; c < 4; c++) {
                float v = accS[nj][c] * SC2;
                accS[nj][c] = v;
                pm[c >> 1] = fmaxf(pm[c >> 1], v);
            }
#pragma unroll
        for (int r = 0; r < 2; r++) {
            pm[r] = fmaxf(pm[r], __shfl_xor_sync(0xffffffffu, pm[r], 1));
            pm[r] = fmaxf(pm[r], __shfl_xor_sync(0xffffffffu, pm[r], 2));
        }
#pragma unroll
        for (int nj = 0; nj < 8; nj++)
#pragma unroll
            for (int c = 0; c < 4; c++) {
                float p = ex2(accS[nj][c] - pm[c >> 1]);
                accS[nj][c] = p;
                ps[c >> 1] += p;
            }
#pragma unroll
        for (int r = 0; r < 2; r++) {
            ps[r] += __shfl_xor_sync(0xffffffffu, ps[r], 1);
            ps[r] += __shfl_xor_sync(0xffffffffu, ps[r], 2);
        }
        float cf[2], corr[2];
#pragma unroll
        for (int r = 0; r < 2; r++) {
            float mnew = fmaxf(m_run[r], pm[r]);
            corr[r] = ex2(m_run[r] - mnew);
            cf[r]   = ex2(pm[r] - mnew);
            l_run[r] = l_run[r] * corr[r] + ps[r] * cf[r];
            m_run[r] = mnew;
        }
#pragma unroll
        for (int nj = 0; nj < 16; nj++)
#pragma unroll
            for (int c = 0; c < 4; c++)
                accO[nj][c] *= corr[c >> 1];

        uint32_t Pa[4][4];
#pragma unroll
        for (int kc = 0; kc < 4; kc++) {
            Pa[kc][0] = pack2(accS[2*kc][0]   * cf[0], accS[2*kc][1]   * cf[0]);
            Pa[kc][1] = pack2(accS[2*kc][2]   * cf[1], accS[2*kc][3]   * cf[1]);
            Pa[kc][2] = pack2(accS[2*kc+1][0] * cf[0], accS[2*kc+1][1] * cf[0]);
            Pa[kc][3] = pack2(accS[2*kc+1][2] * cf[1], accS[2*kc+1][3] * cf[1]);
        }

#pragma unroll
        for (int kc2 = 0; kc2 < 2; kc2++)
#pragma unroll
            for (int nh = 0; nh < 2; nh++) {
                uint32_t bb[8][4];
#pragma unroll
                for (int nj = 0; nj < 8; nj++)
                    ldsm4t(bb[nj], Vb + ((kc2 * 32 + (l >> 3) * 8 + (l & 7)) * 136
                                         + (nh * 8 + nj) * 8) * 2);
#pragma unroll
                for (int kc = 0; kc < 2; kc++)
#pragma unroll
                    for (int nj = 0; nj < 8; nj++)
                        mma16(accO[nh * 8 + nj], Pa[kc2 * 2 + kc],
                              bb[nj][2 * kc], bb[nj][2 * kc + 1]);
            }

        if (kt < 31) {
            CP_WAIT0();
            __syncthreads();
            if (kt < 30) { loadKV(kt + 2, cur); CP_COMMIT(); }
        }
    }

    float inv0 = 1.f / l_run[0], inv1 = 1.f / l_run[1];
    int row0 = q0 + wid * 16 + lr;
#pragma unroll
    for (int nj = 0; nj < 16; nj++) {
        int col = h * Dhc + nj * 8 + 2 * lo;
        *(__half2*)(go + (size_t)(b * Lc + row0) * Dc + col) =
            __floats2half2_rn(accO[nj][0] * inv0, accO[nj][1] * inv0);
        *(__half2*)(go + (size_t)(b * Lc + row0 + 8) * Dc + col) =
            __floats2half2_rn(accO[nj][2] * inv1, accO[nj][3] * inv1);
    }
}

// ================================ host ========================================
extern "C" void kernel_launch(void* const* d_in, const int* in_sizes, int n_in,
                              void* d_out, int out_size) {
    const float* hidden = (const float*)d_in[0];
    const float* temb   = (const float*)d_in[1];
    const float* w_ln   = (const float*)d_in[2];
    const float* w_mod  = (const float*)d_in[3];
    const float* b_mod  = (const float*)d_in[4];
    const float* wq     = (const float*)d_in[5];
    const float* wk     = (const float*)d_in[6];
    const float* wv     = (const float*)d_in[7];
    const float* wo     = (const float*)d_in[8];
    const float* qn     = (const float*)d_in[9];
    const float* kn     = (const float*)d_in[10];
    const float* cos1   = (const float*)d_in[11];
    const float* sin1   = (const float*)d_in[12];
    const float* rope3  = (const float*)d_in[13];
    const int*   mpos   = (const int*)d_in[14];
    float* out = (float*)d_out;

    void *pxm, *pqkv, *po, *pwT, *pwoT;
    cudaGetSymbolAddress(&pxm,  g_xmh);
    cudaGetSymbolAddress(&pqkv, g_qkvh);
    cudaGetSymbolAddress(&po,   g_oh);
    cudaGetSymbolAddress(&pwT,  g_wTh);
    cudaGetSymbolAddress(&pwoT, g_woTh);

    // static side-stream + events for graph fork-join (created on first,
    // non-captured, call; reused deterministically afterwards)
    static cudaStream_t s1 = nullptr;
    static cudaEvent_t ev0 = nullptr, ev1 = nullptr;
    if (!s1) {
        cudaStreamCreateWithFlags(&s1, cudaStreamNonBlocking);
        cudaEventCreateWithFlags(&ev0, cudaEventDisableTiming);
        cudaEventCreateWithFlags(&ev1, cudaEventDisableTiming);
    }

    cudaFuncSetAttribute(k_mma<1>, cudaFuncAttributeMaxDynamicSharedMemorySize, MMASMEM);
    cudaFuncSetAttribute(k_mma<2>, cudaFuncAttributeMaxDynamicSharedMemorySize, MMASMEM);
    cudaFuncSetAttribute(k_flash, cudaFuncAttributeMaxDynamicSharedMemorySize, FSMEM);

    // fork: transposes on s1, concurrent with k_mod -> k_rmsmod on main stream
    cudaEventRecord(ev0, 0);
    cudaStreamWaitEvent(s1, ev0, 0);
    k_transpose4<<<dim3(64, 64, 4), dim3(32, 8), 0, s1>>>(wq, wk, wv, wo);
    cudaEventRecord(ev1, s1);

    k_mod<<<dim3(D3c / 64, Bc), 256>>>(temb, w_mod, b_mod);
    k_rmsmod<<<Bc * Lc, 256>>>(hidden, w_ln);

    cudaStreamWaitEvent(0, ev1, 0);   // join before QKV GEMM

    // fused QKV GEMM + per-head RMSNorm + mixed RoPE epilogue (half out)
    k_mma<2><<<dim3(QKVN / 128, (Bc * Lc) / 128), 256, MMASMEM>>>(
        (const __half*)pxm, (const __half*)pwT, pqkv, QKVN, Dc, nullptr,
        cos1, sin1, rope3, qn, kn, mpos);

    k_flash<<<dim3(Lc / 64, Hc, Bc), 128, FSMEM>>>((__half*)po);

    // output projection + residual/gate epilogue (float out)
    k_mma<1><<<dim3(Dc / 128, (Bc * Lc) / 128), 256, MMASMEM>>>(
        (const __half*)po, (const __half*)pwoT, out, Dc, Dc, hidden);
}